// round 6
// baseline (speedup 1.0000x reference)
#include <cuda_runtime.h>

// GazeLSTM: N=8192 rows, L=32 steps, H=256, 4H=1024, IN=2, OUT=128.
// Persistent-state kernel, 128 CTAs x 256 threads, 64 rows/CTA.
// Inner product uses packed fma.rn.f32x2 (FFMA2) pairing consecutive k.

#define Hh      256
#define FOURH   1024
#define LSTEPS  32
#define NB      64
#define NCTA    128
#define PADK    258       // even pitch -> 8B-aligned (k,k+1) pairs
#define KT      64        // k's per staged panel
#define OUTD    128
#define NPANEL  36        // 32 gate panels (8 m x 4 kt) + 4 FC panels

// ---- prologue-built weights (module-scope device arrays; no runtime alloc) ----
// pair layout: g_Wt2[(k2*1024 + col)*2 + p] = W_hh[(q*256+j)][2*k2+p], col=j*4+q
__device__ float g_Wt2[Hh * FOURH];
__device__ float g_bias[FOURH];            // bias[j*4+q] = b_ih[g]+b_hh[g]
__device__ float g_Wihp[FOURH * 2];        // Wihp[j*4+q][s] = W_ih[g][s]
__device__ float g_fcT2[Hh * OUTD];        // g_fcT2[(k2*128+o)*2+p] = fc_w[o][2*k2+p]

__global__ void prep_kernel(const float* __restrict__ W_ih,
                            const float* __restrict__ W_hh,
                            const float* __restrict__ b_ih,
                            const float* __restrict__ b_hh,
                            const float* __restrict__ fc_w) {
    int idx = blockIdx.x * blockDim.x + threadIdx.x;
    int stride = gridDim.x * blockDim.x;
    for (int f = idx; f < Hh * FOURH; f += stride) {
        int k2 = f >> 11, rem = f & 2047;
        int col = rem >> 1, p = rem & 1;
        int j = col >> 2, q = col & 3;
        g_Wt2[f] = W_hh[(q * Hh + j) * Hh + (2 * k2 + p)];
    }
    for (int f = idx; f < Hh * OUTD; f += stride) {
        int k2 = f >> 8, rem = f & 255;
        int o = rem >> 1, p = rem & 1;
        g_fcT2[f] = fc_w[o * Hh + (2 * k2 + p)];
    }
    if (idx < FOURH) {
        int j = idx >> 2, q = idx & 3;
        int g = q * Hh + j;
        g_bias[idx]         = b_ih[g] + b_hh[g];
        g_Wihp[idx * 2 + 0] = W_ih[g * 2 + 0];
        g_Wihp[idx * 2 + 1] = W_ih[g * 2 + 1];
    }
}

__device__ __forceinline__ void fma2(unsigned long long& d,
                                     unsigned long long a,
                                     unsigned long long b) {
    asm("fma.rn.f32x2 %0, %1, %2, %0;" : "+l"(d) : "l"(a), "l"(b));
}
__device__ __forceinline__ unsigned long long pack2(float lo, float hi) {
    unsigned long long r;
    asm("mov.b64 %0, {%1, %2};" : "=l"(r) : "f"(lo), "f"(hi));
    return r;
}
__device__ __forceinline__ float fold2(unsigned long long v) {
    float lo, hi;
    asm("mov.b64 {%0, %1}, %2;" : "=f"(lo), "=f"(hi) : "l"(v));
    return lo + hi;
}
__device__ __forceinline__ float sigf(float v) {
    return __fdividef(1.0f, 1.0f + __expf(-v));
}
__device__ __forceinline__ float tanhfast(float v) {
    float e = __expf(-2.0f * v);
    return __fdividef(1.0f - e, 1.0f + e);
}

// panel source address (float4 granularity), p in [0, NPANEL)
__device__ __forceinline__ const float4* panel_src(int p, int e4) {
    if (p < 32) {
        int m = p >> 2, kt = p & 3;
        int k2g = kt * 32 + (e4 >> 6);
        return reinterpret_cast<const float4*>(
            g_Wt2 + (size_t)k2g * 2048 + m * 256 + (e4 & 63) * 4);
    } else {
        int kt = p - 32;
        int k2g = kt * 32 + (e4 >> 6);
        return reinterpret_cast<const float4*>(
            g_fcT2 + (size_t)k2g * 256 + (e4 & 63) * 4);
    }
}

// smem floats: H dbl buf 2*64*258=33024, panel 8192, C 16384  -> 230,400 B
#define SMEM_FLOATS (2 * NB * PADK + (KT / 2) * 256 + NB * Hh)

__global__ __launch_bounds__(256, 1)
void lstm_kernel(const float* __restrict__ x,     // [8192][32][2]
                 const float* __restrict__ fc_b,  // [128]
                 float* __restrict__ out) {       // [8192][32][128]
    extern __shared__ float sm[];
    float* Hbuf0 = sm;                       // [64][258]
    float* Hbuf1 = sm + NB * PADK;
    float* Wp    = sm + 2 * NB * PADK;       // [32 k2][256] pair-interleaved
    float* Cs    = Wp + (KT / 2) * 256;      // [64][256]

    const int tx = threadIdx.x;
    const int ty = tx >> 5;        // warp id: row group
    const int tj = tx & 31;
    const int rowbase = ty * 8;
    const int r0 = blockIdx.x * NB;

    for (int i = tx; i < NB * PADK; i += 256) Hbuf0[i] = 0.0f;
    for (int i = tx; i < NB * Hh;  i += 256) Cs[i] = 0.0f;

    // prestage panel 0 (gates m=0, kt=0)
    {
        float4 pf[8];
#pragma unroll
        for (int i = 0; i < 8; ++i) pf[i] = __ldg(panel_src(0, tx + i * 256));
        __syncthreads();
#pragma unroll
        for (int i = 0; i < 8; ++i)
            reinterpret_cast<float4*>(Wp)[tx + i * 256] = pf[i];
        __syncthreads();
    }

    const float4 fb = *reinterpret_cast<const float4*>(fc_b + tj * 4);
    int pcur = 0;

#pragma unroll 1
    for (int l = 0; l < LSTEPS; ++l) {
        float* cur = (l & 1) ? Hbuf1 : Hbuf0;
        float* nxt = (l & 1) ? Hbuf0 : Hbuf1;

        float x0[8], x1[8];
#pragma unroll
        for (int ri = 0; ri < 8; ++ri) {
            const float* xp = x + (size_t)(r0 + rowbase + ri) * (LSTEPS * 2) + l * 2;
            x0[ri] = __ldg(xp);
            x1[ri] = __ldg(xp + 1);
        }

        // ---- gates: 8 chunks of 128 permuted cols ----
#pragma unroll 1
        for (int m = 0; m < 8; ++m) {
            const int j = m * 32 + tj;
            const float4 wA = *reinterpret_cast<const float4*>(g_Wihp + j * 8);
            const float4 wB = *reinterpret_cast<const float4*>(g_Wihp + j * 8 + 4);
            const float4 bs = *reinterpret_cast<const float4*>(g_bias + j * 4);

            unsigned long long acc[8][4];
#pragma unroll
            for (int ri = 0; ri < 8; ++ri) {
                acc[ri][0] = pack2(bs.x + x0[ri] * wA.x + x1[ri] * wA.y, 0.0f);
                acc[ri][1] = pack2(bs.y + x0[ri] * wA.z + x1[ri] * wA.w, 0.0f);
                acc[ri][2] = pack2(bs.z + x0[ri] * wB.x + x1[ri] * wB.y, 0.0f);
                acc[ri][3] = pack2(bs.w + x0[ri] * wB.z + x1[ri] * wB.w, 0.0f);
            }

#pragma unroll 1
            for (int kt = 0; kt < 4; ++kt) {
                // register-prefetch next panel while computing this one
                const int pn = (pcur + 1 == NPANEL) ? 0 : pcur + 1;
                float4 pf[8];
#pragma unroll
                for (int i = 0; i < 8; ++i)
                    pf[i] = __ldg(panel_src(pn, tx + i * 256));

                const float* arow = cur + kt * KT;  // + row*PADK
#pragma unroll 8
                for (int kk2 = 0; kk2 < KT / 2; ++kk2) {
                    const ulonglong2 B0 = *reinterpret_cast<const ulonglong2*>(
                        Wp + kk2 * 256 + tj * 8);
                    const ulonglong2 B1 = *reinterpret_cast<const ulonglong2*>(
                        Wp + kk2 * 256 + tj * 8 + 4);
#pragma unroll
                    for (int ri = 0; ri < 8; ++ri) {
                        const unsigned long long a2 =
                            *reinterpret_cast<const unsigned long long*>(
                                arow + (rowbase + ri) * PADK + kk2 * 2);
                        fma2(acc[ri][0], a2, B0.x);
                        fma2(acc[ri][1], a2, B0.y);
                        fma2(acc[ri][2], a2, B1.x);
                        fma2(acc[ri][3], a2, B1.y);
                    }
                }
                __syncthreads();
#pragma unroll
                for (int i = 0; i < 8; ++i)
                    reinterpret_cast<float4*>(Wp)[tx + i * 256] = pf[i];
                __syncthreads();
                pcur = pn;
            }

            // nonlinearity + state (gate order i,f,g,o). H/C are warp-private.
#pragma unroll
            for (int ri = 0; ri < 8; ++ri) {
                const int cidx = (rowbase + ri) * Hh + j;
                const float ig = sigf(fold2(acc[ri][0]));
                const float fg = sigf(fold2(acc[ri][1]));
                const float gg = tanhfast(fold2(acc[ri][2]));
                const float og = sigf(fold2(acc[ri][3]));
                const float cn = fg * Cs[cidx] + ig * gg;
                Cs[cidx] = cn;
                nxt[(rowbase + ri) * PADK + j] = og * tanhfast(cn);
            }
            __syncwarp();
        }

        // ---- FC: 128 outputs, o = tj*4+q ----
        unsigned long long facc[8][4];
#pragma unroll
        for (int ri = 0; ri < 8; ++ri) {
            facc[ri][0] = pack2(fb.x, 0.0f);
            facc[ri][1] = pack2(fb.y, 0.0f);
            facc[ri][2] = pack2(fb.z, 0.0f);
            facc[ri][3] = pack2(fb.w, 0.0f);
        }
#pragma unroll 1
        for (int kt = 0; kt < 4; ++kt) {
            const int pn = (pcur + 1 == NPANEL) ? 0 : pcur + 1;
            float4 pf[8];
#pragma unroll
            for (int i = 0; i < 8; ++i)
                pf[i] = __ldg(panel_src(pn, tx + i * 256));

            const float* arow = nxt + kt * KT;
#pragma unroll 8
            for (int kk2 = 0; kk2 < KT / 2; ++kk2) {
                const ulonglong2 B0 = *reinterpret_cast<const ulonglong2*>(
                    Wp + kk2 * 256 + tj * 8);
                const ulonglong2 B1 = *reinterpret_cast<const ulonglong2*>(
                    Wp + kk2 * 256 + tj * 8 + 4);
#pragma unroll
                for (int ri = 0; ri < 8; ++ri) {
                    const unsigned long long a2 =
                        *reinterpret_cast<const unsigned long long*>(
                            arow + (rowbase + ri) * PADK + kk2 * 2);
                    fma2(facc[ri][0], a2, B0.x);
                    fma2(facc[ri][1], a2, B0.y);
                    fma2(facc[ri][2], a2, B1.x);
                    fma2(facc[ri][3], a2, B1.y);
                }
            }
            __syncthreads();
#pragma unroll
            for (int i = 0; i < 8; ++i)
                reinterpret_cast<float4*>(Wp)[tx + i * 256] = pf[i];
            __syncthreads();
            pcur = pn;
        }

#pragma unroll
        for (int ri = 0; ri < 8; ++ri) {
            const int n = r0 + rowbase + ri;
            float4 v;
            v.x = fold2(facc[ri][0]);
            v.y = fold2(facc[ri][1]);
            v.z = fold2(facc[ri][2]);
            v.w = fold2(facc[ri][3]);
            *reinterpret_cast<float4*>(
                out + (size_t)n * (LSTEPS * OUTD) + l * OUTD + tj * 4) = v;
        }
    }
}

extern "C" void kernel_launch(void* const* d_in, const int* in_sizes, int n_in,
                              void* d_out, int out_size) {
    const float* x    = (const float*)d_in[0];
    const float* W_ih = (const float*)d_in[1];
    const float* W_hh = (const float*)d_in[2];
    const float* b_ih = (const float*)d_in[3];
    const float* b_hh = (const float*)d_in[4];
    const float* fc_w = (const float*)d_in[5];
    const float* fc_b = (const float*)d_in[6];
    float* out = (float*)d_out;

    prep_kernel<<<128, 256>>>(W_ih, W_hh, b_ih, b_hh, fc_w);

    const size_t smem_bytes = (size_t)SMEM_FLOATS * sizeof(float);  // 230,400 B
    cudaFuncSetAttribute(lstm_kernel, cudaFuncAttributeMaxDynamicSharedMemorySize,
                         (int)smem_bytes);
    lstm_kernel<<<NCTA, 256, smem_bytes>>>(x, fc_b, out);
}

// round 11
// speedup vs baseline: 2.5537x; 2.5537x over previous
#include <cuda_runtime.h>
#include <cuda_fp16.h>
#include <cstdint>

// GazeLSTM via mma.sync.m16n8k16 split-fp16 (3-term). 128 CTAs x 256 thr, M=64 rows/CTA.
// h kept in smem as A fragments (hi/lo planes, step-parity double buffer); W streamed as
// prep-formatted B fragments via cp.async; c-state per-thread.

#define LSTEPS   32
#define NCTA     128
#define NC_STEP  36                    // 32 gate chunks (8 jb x 4 q) + 4 FC chunks, N=32
#define TOTAL_CH (LSTEPS * NC_STEP)    // 1152
#define CHUNK_B  32768                 // B frags per chunk: 16s x 4nt x 2pl x 32ln x 8B

// smem byte offsets
#define SMA      0                     // A frags: 2 bufs x 65536
#define SMA_BUF  65536                 //   per buf: [plane(32768)][ktile*2048][wr*512][lane*16]
#define SMB      131072                // B frags: 2 bufs x 32768
#define SMBI     196608                // bias [1024]f
#define SMW0     200704                // w_ih col 0 [1024]f
#define SMW1     204800                // w_ih col 1 [1024]f
#define SMFCB    208896                // fc_b [128]f
#define SMEM_TOTAL 209408

// ---------------- prologue-built weights ----------------
__device__ __align__(256) uint32_t g_Bu[NC_STEP * (CHUNK_B / 4)];
__device__ float g_biasN[1024], g_w0N[1024], g_w1N[1024];

__device__ __forceinline__ uint32_t ph2(float a, float b) {
    __half2 h = __floats2half2_rn(a, b);     // .x = a = low 16 bits (even k)
    return *reinterpret_cast<uint32_t*>(&h);
}

__global__ void prep_kernel(const float* __restrict__ W_ih,
                            const float* __restrict__ W_hh,
                            const float* __restrict__ b_ih,
                            const float* __restrict__ b_hh,
                            const float* __restrict__ fc_w) {
    int idx = blockIdx.x * blockDim.x + threadIdx.x;
    int stride = gridDim.x * blockDim.x;
    // B fragment u32 index within chunk: ((s*4 + nt)*2 + plane)*64 + lane*2 + reg
    // frag: reg r holds B[k = s*16 + 2*(lane&3) + r*8 + {0,1}][n = nt*8 + (lane>>2)]
    for (int u = idx; u < NC_STEP * (CHUNK_B / 4); u += stride) {
        int c = u >> 13, rem = u & 8191;
        int reg = rem & 1, lane = (rem >> 1) & 31;
        int plane = (rem >> 6) & 1, nt = (rem >> 7) & 3, s = rem >> 9;
        int n_local = nt * 8 + (lane >> 2);
        int k0 = s * 16 + (lane & 3) * 2 + reg * 8;
        const float* srcrow;
        if (c < 32) {
            int jb = c >> 2, q = c & 3;                   // chunk = (j-block, gate)
            srcrow = W_hh + (size_t)(q * 256 + jb * 32 + n_local) * 256;
        } else {
            srcrow = fc_w + (size_t)((c - 32) * 32 + n_local) * 256;
        }
        float v0 = srcrow[k0], v1 = srcrow[k0 + 1];
        uint32_t val;
        if (plane == 0) {
            val = ph2(v0, v1);
        } else {
            float l0 = v0 - __half2float(__float2half_rn(v0));
            float l1 = v1 - __half2float(__float2half_rn(v1));
            val = ph2(l0, l1);
        }
        g_Bu[u] = val;
    }
    for (int g = idx; g < 1024; g += stride) {
        g_biasN[g] = b_ih[g] + b_hh[g];
        g_w0N[g]   = W_ih[g * 2 + 0];
        g_w1N[g]   = W_ih[g * 2 + 1];
    }
}

// ---------------- device helpers ----------------
__device__ __forceinline__ uint32_t smem_u32(const void* p) {
    uint32_t a;
    asm("{ .reg .u64 t; cvta.to.shared.u64 t, %1; cvt.u32.u64 %0, t; }" : "=r"(a) : "l"(p));
    return a;
}
__device__ __forceinline__ void mma16816(float (&d)[4], const uint4& a, const uint2& b) {
    asm("mma.sync.aligned.m16n8k16.row.col.f32.f16.f16.f32 "
        "{%0,%1,%2,%3},{%4,%5,%6,%7},{%8,%9},{%0,%1,%2,%3};"
        : "+f"(d[0]), "+f"(d[1]), "+f"(d[2]), "+f"(d[3])
        : "r"(a.x), "r"(a.y), "r"(a.z), "r"(a.w), "r"(b.x), "r"(b.y));
}
#define CP16(dst, src) \
    asm volatile("cp.async.cg.shared.global [%0], [%1], 16;" :: "r"(dst), "l"(src) : "memory")
#define CP_COMMIT() asm volatile("cp.async.commit_group;" ::: "memory")
#define CP_WAIT0()  asm volatile("cp.async.wait_group 0;" ::: "memory")

__device__ __forceinline__ void stage_chunk(uint32_t dst, const uint8_t* gsrc, int tx) {
    uint32_t d = dst + tx * 16;
    uint64_t s = (uint64_t)__cvta_generic_to_global(gsrc) + tx * 16;
#pragma unroll
    for (int i = 0; i < 8; ++i) CP16(d + i * 4096, s + i * 4096);
    CP_COMMIT();
}

__device__ __forceinline__ float sigf(float v) {
    return __fdividef(1.0f, 1.0f + __expf(-v));
}
__device__ __forceinline__ float tanhfast(float v) {
    float e = __expf(-2.0f * v);
    return __fdividef(1.0f - e, 1.0f + e);
}

// one N=32 chunk: D += Ahi*Bhi + Ahi*Blo + Alo*Bhi over K=256 (16 k-steps)
__device__ __forceinline__ void chunk_mma(const uint8_t* sm, uint32_t aoff, uint32_t boff,
                                          int wr, int wc, int lane, float (&D)[2][4]) {
    float Da[2][4] = {}, Db[2][4] = {}, Dc[2][4] = {};
    const uint8_t* ah = sm + aoff + wr * 512 + lane * 16;
    const uint8_t* bb = sm + boff + wc * 1024 + lane * 8;
#pragma unroll 4
    for (int s = 0; s < 16; ++s) {
        const uint4 Ah  = *reinterpret_cast<const uint4*>(ah + s * 2048);
        const uint4 Al  = *reinterpret_cast<const uint4*>(ah + 32768 + s * 2048);
        const uint2 Bh0 = *reinterpret_cast<const uint2*>(bb + s * 2048);
        const uint2 Bl0 = *reinterpret_cast<const uint2*>(bb + s * 2048 + 256);
        const uint2 Bh1 = *reinterpret_cast<const uint2*>(bb + s * 2048 + 512);
        const uint2 Bl1 = *reinterpret_cast<const uint2*>(bb + s * 2048 + 768);
        mma16816(Da[0], Ah, Bh0); mma16816(Db[0], Ah, Bl0); mma16816(Dc[0], Al, Bh0);
        mma16816(Da[1], Ah, Bh1); mma16816(Db[1], Ah, Bl1); mma16816(Dc[1], Al, Bh1);
    }
#pragma unroll
    for (int nt = 0; nt < 2; ++nt)
#pragma unroll
        for (int i = 0; i < 4; ++i)
            D[nt][i] += Da[nt][i] + Db[nt][i] + Dc[nt][i];
}

__global__ __launch_bounds__(256, 1)
void lstm_kernel(const float* __restrict__ x,     // [8192][32][2]
                 const float* __restrict__ fc_b,  // [128]
                 float* __restrict__ out) {       // [8192][32][128]
    extern __shared__ uint8_t sm[];
    const uint32_t smb = smem_u32(sm);
    const int tx = threadIdx.x;
    const int w = tx >> 5, lane = tx & 31;
    const int wr = w >> 1, wc = w & 1;          // 4x2 warp tiling (m x n)
    const int g = lane >> 2, t = lane & 3;
    const uint8_t* gBu = reinterpret_cast<const uint8_t*>(g_Bu);

    float* sbias = reinterpret_cast<float*>(sm + SMBI);
    float* sw0   = reinterpret_cast<float*>(sm + SMW0);
    float* sw1   = reinterpret_cast<float*>(sm + SMW1);
    float* sfcb  = reinterpret_cast<float*>(sm + SMFCB);

    for (int i = tx; i < 1024; i += 256) {
        sbias[i] = g_biasN[i];
        sw0[i]   = g_w0N[i];
        sw1[i]   = g_w1N[i];
    }
    if (tx < 128) sfcb[tx] = fc_b[tx];
    // zero A buf 0 (h_{-1} = 0)
    {
        uint32_t* a32 = reinterpret_cast<uint32_t*>(sm);
        for (int i = tx; i < 16384; i += 256) a32[i] = 0u;
    }
    // prestage chunk 0 into B buf 0
    stage_chunk(smb + SMB, gBu, tx);
    CP_WAIT0();
    __syncthreads();

    const int row0 = blockIdx.x * 64 + wr * 16 + g;
    const int row1 = row0 + 8;

    float c_st[8][8];
#pragma unroll
    for (int i = 0; i < 8; ++i)
#pragma unroll
        for (int j = 0; j < 8; ++j) c_st[i][j] = 0.0f;

#pragma unroll 1
    for (int l = 0; l < LSTEPS; ++l) {
        const int p = l & 1;
        const int gcb = l * NC_STEP;
        const float2 xv0 = __ldg(reinterpret_cast<const float2*>(x + (size_t)row0 * 64 + l * 2));
        const float2 xv1 = __ldg(reinterpret_cast<const float2*>(x + (size_t)row1 * 64 + l * 2));

        // -------- gates: 8 j-blocks x 4 gate chunks --------
#pragma unroll 1
        for (int jb = 0; jb < 8; ++jb) {
            float D[4][2][4];
#pragma unroll
            for (int q = 0; q < 4; ++q)
#pragma unroll
                for (int nt = 0; nt < 2; ++nt)
#pragma unroll
                    for (int i = 0; i < 4; ++i) D[q][nt][i] = 0.0f;

#pragma unroll
            for (int q = 0; q < 4; ++q) {
                const int gc = gcb + jb * 4 + q;
                if (gc + 1 < TOTAL_CH)
                    stage_chunk(smb + SMB + ((gc + 1) & 1) * CHUNK_B,
                                gBu + (size_t)((gc + 1) % NC_STEP) * CHUNK_B, tx);
                chunk_mma(sm, p * SMA_BUF, SMB + (gc & 1) * CHUNK_B, wr, wc, lane, D[q]);
                CP_WAIT0();
                __syncthreads();
            }

            // epilogue: gates -> c,h for this thread's 8 (row,col) positions
            float h[2][4];
#pragma unroll
            for (int nt = 0; nt < 2; ++nt) {
#pragma unroll
                for (int ci = 0; ci < 4; ++ci) {
                    const int nl = (2 * wc + nt) * 8 + 2 * t + (ci & 1);
                    const float2 xv = (ci & 2) ? xv1 : xv0;
                    const int gb = jb * 32 + nl;
                    const float gi = D[0][nt][ci] + sbias[gb]       + xv.x * sw0[gb]       + xv.y * sw1[gb];
                    const float gf = D[1][nt][ci] + sbias[256 + gb] + xv.x * sw0[256 + gb] + xv.y * sw1[256 + gb];
                    const float gg = D[2][nt][ci] + sbias[512 + gb] + xv.x * sw0[512 + gb] + xv.y * sw1[512 + gb];
                    const float go = D[3][nt][ci] + sbias[768 + gb] + xv.x * sw0[768 + gb] + xv.y * sw1[768 + gb];
                    const float co = c_st[jb][nt * 4 + ci];
                    const float cn = sigf(gf) * co + sigf(gi) * tanhfast(gg);
                    c_st[jb][nt * 4 + ci] = cn;
                    h[nt][ci] = sigf(go) * tanhfast(cn);
                }
            }
            // split to fp16 hi/lo and store as next-step A fragments (ktile = jb*2+wc)
            uint32_t hi[4], lo[4];
#pragma unroll
            for (int r = 0; r < 4; ++r) {
                const int nt = r >> 1, base = (r & 1) * 2;
                const float a = h[nt][base], b = h[nt][base + 1];
                const __half ha = __float2half_rn(a), hb = __float2half_rn(b);
                const __half2 hh = __halves2half2(ha, hb);
                hi[r] = *reinterpret_cast<const uint32_t*>(&hh);
                const __half2 ll = __floats2half2_rn(a - __half2float(ha), b - __half2float(hb));
                lo[r] = *reinterpret_cast<const uint32_t*>(&ll);
            }
            {
                const int kt = jb * 2 + wc;
                uint8_t* adst = sm + (p ^ 1) * SMA_BUF + kt * 2048 + wr * 512 + lane * 16;
                *reinterpret_cast<uint4*>(adst)         = make_uint4(hi[0], hi[1], hi[2], hi[3]);
                *reinterpret_cast<uint4*>(adst + 32768) = make_uint4(lo[0], lo[1], lo[2], lo[3]);
            }
        }
        __syncthreads();   // all h_t fragments visible before FC reads them

        // -------- FC: 4 chunks on h_t (A buf p^1) --------
#pragma unroll 1
        for (int fcc = 0; fcc < 4; ++fcc) {
            const int gc = gcb + 32 + fcc;
            if (gc + 1 < TOTAL_CH)
                stage_chunk(smb + SMB + ((gc + 1) & 1) * CHUNK_B,
                            gBu + (size_t)((gc + 1) % NC_STEP) * CHUNK_B, tx);
            float Df[2][4];
#pragma unroll
            for (int nt = 0; nt < 2; ++nt)
#pragma unroll
                for (int i = 0; i < 4; ++i) Df[nt][i] = 0.0f;
            chunk_mma(sm, (p ^ 1) * SMA_BUF, SMB + (gc & 1) * CHUNK_B, wr, wc, lane, Df);
#pragma unroll
            for (int nt = 0; nt < 2; ++nt) {
                const int cb = fcc * 32 + (2 * wc + nt) * 8 + 2 * t;
                const float2 v0 = make_float2(Df[nt][0] + sfcb[cb], Df[nt][1] + sfcb[cb + 1]);
                const float2 v1 = make_float2(Df[nt][2] + sfcb[cb], Df[nt][3] + sfcb[cb + 1]);
                *reinterpret_cast<float2*>(out + (size_t)row0 * (LSTEPS * 128) + l * 128 + cb) = v0;
                *reinterpret_cast<float2*>(out + (size_t)row1 * (LSTEPS * 128) + l * 128 + cb) = v1;
            }
            CP_WAIT0();
            __syncthreads();
        }
    }
}

extern "C" void kernel_launch(void* const* d_in, const int* in_sizes, int n_in,
                              void* d_out, int out_size) {
    const float* x    = (const float*)d_in[0];
    const float* W_ih = (const float*)d_in[1];
    const float* W_hh = (const float*)d_in[2];
    const float* b_ih = (const float*)d_in[3];
    const float* b_hh = (const float*)d_in[4];
    const float* fc_w = (const float*)d_in[5];
    const float* fc_b = (const float*)d_in[6];
    float* out = (float*)d_out;

    prep_kernel<<<288, 256>>>(W_ih, W_hh, b_ih, b_hh, fc_w);

    cudaFuncSetAttribute(lstm_kernel, cudaFuncAttributeMaxDynamicSharedMemorySize, SMEM_TOTAL);
    lstm_kernel<<<NCTA, 256, SMEM_TOTAL>>>(x, fc_b, out);
}

// round 12
// speedup vs baseline: 3.5949x; 1.4077x over previous
#include <cuda_runtime.h>
#include <cuda_fp16.h>
#include <cstdint>

// GazeLSTM via mma.sync.m16n8k16, 2-term split (h fp16, W = Whi + Wlo fp16 planes).
// 128 CTAs x 256 thr, M=64 rows/CTA, N=64 chunks (16 gate + 2 FC per step).
// h kept in smem as A fragments (single fp16 plane, step-parity double buffer).

#define LSTEPS   32
#define NCTA     128
#define NC_STEP  18                    // 16 gate chunks (4 jb x 4 q) + 2 FC chunks, N=64
#define TOTAL_CH (LSTEPS * NC_STEP)    // 576
#define CHUNK_B  65536                 // B frags: 16s x 8nt x 32lane x 16B (hi/lo interleaved)

// smem byte offsets
#define SMA      0                     // A frags: 2 bufs x 32768
#define SMA_BUF  32768                 //   per buf: [ktile(16)*2048][wr*512][lane*16]
#define SMB      65536                 // B frags: 2 bufs x 65536
#define SMBI     196608                // bias [1024]f
#define SMW0     200704                // w_ih col 0 [1024]f
#define SMW1     204800                // w_ih col 1 [1024]f
#define SMFCB    208896                // fc_b [128]f
#define SMEM_TOTAL 209408

// ---------------- prologue-built weights ----------------
__device__ __align__(256) uint32_t g_Bu[NC_STEP * (CHUNK_B / 4)];
__device__ float g_biasN[1024], g_w0N[1024], g_w1N[1024];

__device__ __forceinline__ uint32_t ph2(float a, float b) {
    __half2 h = __floats2half2_rn(a, b);     // .x = a = low 16 bits (even k)
    return *reinterpret_cast<uint32_t*>(&h);
}

__global__ void prep_kernel(const float* __restrict__ W_ih,
                            const float* __restrict__ W_hh,
                            const float* __restrict__ b_ih,
                            const float* __restrict__ b_hh,
                            const float* __restrict__ fc_w) {
    int idx = blockIdx.x * blockDim.x + threadIdx.x;
    int stride = gridDim.x * blockDim.x;
    // B frag u32 index in chunk: ((s*8 + nt)*32 + lane)*4 + plane*2 + reg
    // value: W[k = s*16 + 2*(lane&3) + reg*8 + {0,1}][n = nt*8 + (lane>>2)], plane hi/lo
    for (int u = idx; u < NC_STEP * (CHUNK_B / 4); u += stride) {
        int c = u >> 14, rem = u & 16383;
        int reg = rem & 1, plane = (rem >> 1) & 1;
        int lane = (rem >> 2) & 31, nt = (rem >> 7) & 7, s = rem >> 10;
        int n_local = nt * 8 + (lane >> 2);
        int k0 = s * 16 + (lane & 3) * 2 + reg * 8;
        const float* srcrow;
        if (c < 16) {
            int jb = c >> 2, q = c & 3;                   // chunk = (j-block of 64, gate)
            srcrow = W_hh + (size_t)(q * 256 + jb * 64 + n_local) * 256;
        } else {
            srcrow = fc_w + (size_t)((c - 16) * 64 + n_local) * 256;
        }
        float v0 = srcrow[k0], v1 = srcrow[k0 + 1];
        uint32_t val;
        if (plane == 0) {
            val = ph2(v0, v1);
        } else {
            float l0 = v0 - __half2float(__float2half_rn(v0));
            float l1 = v1 - __half2float(__float2half_rn(v1));
            val = ph2(l0, l1);
        }
        g_Bu[u] = val;
    }
    for (int g = idx; g < 1024; g += stride) {
        g_biasN[g] = b_ih[g] + b_hh[g];
        g_w0N[g]   = W_ih[g * 2 + 0];
        g_w1N[g]   = W_ih[g * 2 + 1];
    }
}

// ---------------- device helpers ----------------
__device__ __forceinline__ uint32_t smem_u32(const void* p) {
    uint32_t a;
    asm("{ .reg .u64 t; cvta.to.shared.u64 t, %1; cvt.u32.u64 %0, t; }" : "=r"(a) : "l"(p));
    return a;
}
__device__ __forceinline__ void mma16816(float (&d)[4], const uint4& a, uint32_t b0, uint32_t b1) {
    asm("mma.sync.aligned.m16n8k16.row.col.f32.f16.f16.f32 "
        "{%0,%1,%2,%3},{%4,%5,%6,%7},{%8,%9},{%0,%1,%2,%3};"
        : "+f"(d[0]), "+f"(d[1]), "+f"(d[2]), "+f"(d[3])
        : "r"(a.x), "r"(a.y), "r"(a.z), "r"(a.w), "r"(b0), "r"(b1));
}
#define CP16(dst, src) \
    asm volatile("cp.async.cg.shared.global [%0], [%1], 16;" :: "r"(dst), "l"(src) : "memory")
#define CP_COMMIT() asm volatile("cp.async.commit_group;" ::: "memory")
#define CP_WAIT0()  asm volatile("cp.async.wait_group 0;" ::: "memory")

__device__ __forceinline__ void stage_chunk(uint32_t dst, const uint8_t* gsrc, int tx) {
    uint32_t d = dst + tx * 16;
    uint64_t s = (uint64_t)__cvta_generic_to_global(gsrc) + tx * 16;
#pragma unroll
    for (int i = 0; i < 16; ++i) CP16(d + i * 4096, s + i * 4096);
    CP_COMMIT();
}

__device__ __forceinline__ float sigf(float v) {
    return __fdividef(1.0f, 1.0f + __expf(-v));
}
__device__ __forceinline__ float tanhfast(float v) {
    float e = __expf(-2.0f * v);
    return __fdividef(1.0f - e, 1.0f + e);
}

// one N=64 chunk (this warp's N=32 half): D[nt] += A*(Bhi) + A*(Blo), K=256
__device__ __forceinline__ void chunk_mma(const uint8_t* sm, uint32_t aoff, uint32_t boff,
                                          int wr, int wc, int lane, float (&D)[4][4]) {
    float Da[4][4] = {}, Db[4][4] = {};
    const uint8_t* ab = sm + aoff + wr * 512 + lane * 16;
    const uint8_t* bb = sm + boff + wc * 2048 + lane * 16;
#pragma unroll 4
    for (int s = 0; s < 16; ++s) {
        const uint4 A = *reinterpret_cast<const uint4*>(ab + s * 2048);
#pragma unroll
        for (int nt = 0; nt < 4; ++nt) {
            const uint4 B = *reinterpret_cast<const uint4*>(bb + s * 4096 + nt * 512);
            mma16816(Da[nt], A, B.x, B.y);   // hi plane
            mma16816(Db[nt], A, B.z, B.w);   // lo plane
        }
    }
#pragma unroll
    for (int nt = 0; nt < 4; ++nt)
#pragma unroll
        for (int i = 0; i < 4; ++i) D[nt][i] += Da[nt][i] + Db[nt][i];
}

__global__ __launch_bounds__(256, 1)
void lstm_kernel(const float* __restrict__ x,     // [8192][32][2]
                 const float* __restrict__ fc_b,  // [128]
                 float* __restrict__ out) {       // [8192][32][128]
    extern __shared__ uint8_t sm[];
    const uint32_t smb = smem_u32(sm);
    const int tx = threadIdx.x;
    const int w = tx >> 5, lane = tx & 31;
    const int wr = w >> 1, wc = w & 1;          // 4x2 warp tiling (m16-rows x n32-half)
    const int g = lane >> 2, t = lane & 3;
    const uint8_t* gBu = reinterpret_cast<const uint8_t*>(g_Bu);

    float* sbias = reinterpret_cast<float*>(sm + SMBI);
    float* sw0   = reinterpret_cast<float*>(sm + SMW0);
    float* sw1   = reinterpret_cast<float*>(sm + SMW1);
    float* sfcb  = reinterpret_cast<float*>(sm + SMFCB);

    for (int i = tx; i < 1024; i += 256) {
        sbias[i] = g_biasN[i];
        sw0[i]   = g_w0N[i];
        sw1[i]   = g_w1N[i];
    }
    if (tx < 128) sfcb[tx] = fc_b[tx];
    // zero A buf 0 (h_{-1} = 0)
    {
        uint32_t* a32 = reinterpret_cast<uint32_t*>(sm);
        for (int i = tx; i < 8192; i += 256) a32[i] = 0u;
    }
    // prestage chunk 0 into B buf 0
    stage_chunk(smb + SMB, gBu, tx);
    CP_WAIT0();
    __syncthreads();

    const int row0 = blockIdx.x * 64 + wr * 16 + g;
    const int row1 = row0 + 8;

    float c_st[4][16];
#pragma unroll
    for (int i = 0; i < 4; ++i)
#pragma unroll
        for (int j = 0; j < 16; ++j) c_st[i][j] = 0.0f;

#pragma unroll 1
    for (int l = 0; l < LSTEPS; ++l) {
        const int p = l & 1;
        const int gcb = l * NC_STEP;
        const float2 xv0 = __ldg(reinterpret_cast<const float2*>(x + (size_t)row0 * 64 + l * 2));
        const float2 xv1 = __ldg(reinterpret_cast<const float2*>(x + (size_t)row1 * 64 + l * 2));

        // -------- gates: 4 j-blocks (64 j each) x 4 gate chunks --------
#pragma unroll 1
        for (int jb = 0; jb < 4; ++jb) {
            float D[4][4][4];
#pragma unroll
            for (int q = 0; q < 4; ++q)
#pragma unroll
                for (int nt = 0; nt < 4; ++nt)
#pragma unroll
                    for (int i = 0; i < 4; ++i) D[q][nt][i] = 0.0f;

#pragma unroll
            for (int q = 0; q < 4; ++q) {
                const int gc = gcb + jb * 4 + q;
                if (gc + 1 < TOTAL_CH)
                    stage_chunk(smb + SMB + ((gc + 1) & 1) * CHUNK_B,
                                gBu + (size_t)((gc + 1) % NC_STEP) * CHUNK_B, tx);
                chunk_mma(sm, SMA + p * SMA_BUF, SMB + (gc & 1) * CHUNK_B, wr, wc, lane, D[q]);
                CP_WAIT0();
                __syncthreads();
            }

            // epilogue: 16 (row,col) positions per thread
            float h[4][4];
#pragma unroll
            for (int nt = 0; nt < 4; ++nt) {
#pragma unroll
                for (int ci = 0; ci < 4; ++ci) {
                    const int jl = wc * 32 + nt * 8 + 2 * t + (ci & 1);
                    const float2 xv = (ci & 2) ? xv1 : xv0;
                    const int gb = jb * 64 + jl;
                    const float gi = D[0][nt][ci] + sbias[gb]       + xv.x * sw0[gb]       + xv.y * sw1[gb];
                    const float gf = D[1][nt][ci] + sbias[256 + gb] + xv.x * sw0[256 + gb] + xv.y * sw1[256 + gb];
                    const float gg = D[2][nt][ci] + sbias[512 + gb] + xv.x * sw0[512 + gb] + xv.y * sw1[512 + gb];
                    const float go = D[3][nt][ci] + sbias[768 + gb] + xv.x * sw0[768 + gb] + xv.y * sw1[768 + gb];
                    const float co = c_st[jb][nt * 4 + ci];
                    const float cn = sigf(gf) * co + sigf(gi) * tanhfast(gg);
                    c_st[jb][nt * 4 + ci] = cn;
                    h[nt][ci] = sigf(go) * tanhfast(cn);
                }
            }
            // store h as next-step A fragments (fp16 hi only), 2 ktiles per thread
            {
                const int ktA = jb * 4 + wc * 2;
                uint8_t* base = sm + SMA + (p ^ 1) * SMA_BUF + wr * 512 + lane * 16;
                uint4 fa, fbv;
                fa.x  = ph2(h[0][0], h[0][1]);  fa.y  = ph2(h[0][2], h[0][3]);
                fa.z  = ph2(h[1][0], h[1][1]);  fa.w  = ph2(h[1][2], h[1][3]);
                fbv.x = ph2(h[2][0], h[2][1]);  fbv.y = ph2(h[2][2], h[2][3]);
                fbv.z = ph2(h[3][0], h[3][1]);  fbv.w = ph2(h[3][2], h[3][3]);
                *reinterpret_cast<uint4*>(base + (size_t)ktA * 2048)       = fa;
                *reinterpret_cast<uint4*>(base + (size_t)(ktA + 1) * 2048) = fbv;
            }
        }
        __syncthreads();   // all h_t fragments visible before FC reads them

        // -------- FC: 2 chunks (N=64) on h_t (A buf p^1) --------
#pragma unroll
        for (int fcc = 0; fcc < 2; ++fcc) {
            const int gc = gcb + 16 + fcc;
            if (gc + 1 < TOTAL_CH)
                stage_chunk(smb + SMB + ((gc + 1) & 1) * CHUNK_B,
                            gBu + (size_t)((gc + 1) % NC_STEP) * CHUNK_B, tx);
            float Df[4][4];
#pragma unroll
            for (int nt = 0; nt < 4; ++nt)
#pragma unroll
                for (int i = 0; i < 4; ++i) Df[nt][i] = 0.0f;
            chunk_mma(sm, SMA + (p ^ 1) * SMA_BUF, SMB + (gc & 1) * CHUNK_B, wr, wc, lane, Df);
#pragma unroll
            for (int nt = 0; nt < 4; ++nt) {
                const int cb = fcc * 64 + wc * 32 + nt * 8 + 2 * t;
                const float2 v0 = make_float2(Df[nt][0] + sfcb[cb], Df[nt][1] + sfcb[cb + 1]);
                const float2 v1 = make_float2(Df[nt][2] + sfcb[cb], Df[nt][3] + sfcb[cb + 1]);
                *reinterpret_cast<float2*>(out + (size_t)row0 * (LSTEPS * 128) + l * 128 + cb) = v0;
                *reinterpret_cast<float2*>(out + (size_t)row1 * (LSTEPS * 128) + l * 128 + cb) = v1;
            }
            CP_WAIT0();
            __syncthreads();
        }
    }
}

extern "C" void kernel_launch(void* const* d_in, const int* in_sizes, int n_in,
                              void* d_out, int out_size) {
    const float* x    = (const float*)d_in[0];
    const float* W_ih = (const float*)d_in[1];
    const float* W_hh = (const float*)d_in[2];
    const float* b_ih = (const float*)d_in[3];
    const float* b_hh = (const float*)d_in[4];
    const float* fc_w = (const float*)d_in[5];
    const float* fc_b = (const float*)d_in[6];
    float* out = (float*)d_out;

    prep_kernel<<<288, 256>>>(W_ih, W_hh, b_ih, b_hh, fc_w);

    cudaFuncSetAttribute(lstm_kernel, cudaFuncAttributeMaxDynamicSharedMemorySize, SMEM_TOTAL);
    lstm_kernel<<<NCTA, 256, SMEM_TOTAL>>>(x, fc_b, out);
}

// round 13
// speedup vs baseline: 5.7360x; 1.5956x over previous
#include <cuda_runtime.h>
#include <cuda_fp16.h>
#include <cstdint>

// GazeLSTM via mma.sync.m16n8k16, pure fp16 weights (1-term), h fp16 in smem A frags.
// 128 CTAs x 256 thr (8 warps = 2 wr x 4 wc), M=64 rows/CTA, N=64 chunks.
// 4-deep B ring staged by cp.async, one barrier per 2 chunks.

#define LSTEPS   32
#define NCTA     128
#define NC_STEP  18                    // 16 gate chunks (4 jb x 4 q) + 2 FC chunks
#define TOTAL_CH (LSTEPS * NC_STEP)
#define CHUNK_B  32768                 // 16s x 8nt x 32lane x 8B (single fp16 plane)

// smem byte offsets
#define SMA      0                     // A frags: 2 bufs x 32768
#define SMA_BUF  32768
#define SMB      65536                 // B ring: 4 bufs x 32768 -> ends 196608
#define SMBI     196608
#define SMW0     200704
#define SMW1     204800
#define SMFCB    208896
#define SMEM_TOTAL 209408

// ---------------- prologue-built weights ----------------
__device__ __align__(256) uint32_t g_Bu[NC_STEP * (CHUNK_B / 4)];
__device__ float g_biasN[1024], g_w0N[1024], g_w1N[1024];

__device__ __forceinline__ uint32_t ph2(float a, float b) {
    __half2 h = __floats2half2_rn(a, b);     // .x = a = low 16 bits (even k)
    return *reinterpret_cast<uint32_t*>(&h);
}

__global__ void prep_kernel(const float* __restrict__ W_ih,
                            const float* __restrict__ W_hh,
                            const float* __restrict__ b_ih,
                            const float* __restrict__ b_hh,
                            const float* __restrict__ fc_w) {
    int idx = blockIdx.x * blockDim.x + threadIdx.x;
    int stride = gridDim.x * blockDim.x;
    // B frag u32 idx in chunk: ((s*8 + nt)*32 + lane)*2 + reg
    // value: W[k = s*16 + 2*(lane&3) + reg*8 + {0,1}][n = nt*8 + (lane>>2)]
    for (int u = idx; u < NC_STEP * (CHUNK_B / 4); u += stride) {
        int c = u >> 13, rem = u & 8191;
        int reg = rem & 1, lane = (rem >> 1) & 31;
        int nt = (rem >> 6) & 7, s = rem >> 9;
        int n_local = nt * 8 + (lane >> 2);
        int k0 = s * 16 + (lane & 3) * 2 + reg * 8;
        const float* srcrow;
        if (c < 16) {
            int jb = c >> 2, q = c & 3;                   // chunk = (j-block of 64, gate)
            srcrow = W_hh + (size_t)(q * 256 + jb * 64 + n_local) * 256;
        } else {
            srcrow = fc_w + (size_t)((c - 16) * 64 + n_local) * 256;
        }
        g_Bu[u] = ph2(srcrow[k0], srcrow[k0 + 1]);
    }
    for (int g = idx; g < 1024; g += stride) {
        g_biasN[g] = b_ih[g] + b_hh[g];
        g_w0N[g]   = W_ih[g * 2 + 0];
        g_w1N[g]   = W_ih[g * 2 + 1];
    }
}

// ---------------- device helpers ----------------
__device__ __forceinline__ uint32_t smem_u32(const void* p) {
    uint32_t a;
    asm("{ .reg .u64 t; cvta.to.shared.u64 t, %1; cvt.u32.u64 %0, t; }" : "=r"(a) : "l"(p));
    return a;
}
__device__ __forceinline__ void mma16816(float (&d)[4], const uint4& a, uint32_t b0, uint32_t b1) {
    asm("mma.sync.aligned.m16n8k16.row.col.f32.f16.f16.f32 "
        "{%0,%1,%2,%3},{%4,%5,%6,%7},{%8,%9},{%0,%1,%2,%3};"
        : "+f"(d[0]), "+f"(d[1]), "+f"(d[2]), "+f"(d[3])
        : "r"(a.x), "r"(a.y), "r"(a.z), "r"(a.w), "r"(b0), "r"(b1));
}
#define CP16(dst, src) \
    asm volatile("cp.async.cg.shared.global [%0], [%1], 16;" :: "r"(dst), "l"(src) : "memory")
#define CP_COMMIT() asm volatile("cp.async.commit_group;" ::: "memory")
#define CP_WAIT2()  asm volatile("cp.async.wait_group 2;" ::: "memory")

__device__ __forceinline__ void stage_chunk(uint32_t dst, const uint8_t* gsrc, int tx) {
    uint32_t d = dst + tx * 16;
    uint64_t s = (uint64_t)__cvta_generic_to_global(gsrc) + tx * 16;
#pragma unroll
    for (int i = 0; i < 8; ++i) CP16(d + i * 4096, s + i * 4096);
    CP_COMMIT();
}

__device__ __forceinline__ float sigf(float v) {
    return __fdividef(1.0f, 1.0f + __expf(-v));
}
__device__ __forceinline__ float tanhfast(float v) {
    float e = __expf(-2.0f * v);
    return __fdividef(1.0f - e, 1.0f + e);
}

// one N=64 chunk, this warp: rows wr*32..+32 (2 m-frags), cols wc*16..+16 (2 n-tiles)
__device__ __forceinline__ void chunk_mma(const uint8_t* sm, uint32_t aoff, uint32_t boff,
                                          int wr, int wc, int lane, float (&D)[2][2][4]) {
    const uint8_t* ab = sm + aoff + wr * 1024 + lane * 16;
    const uint8_t* bb = sm + boff + wc * 512 + lane * 8;
#pragma unroll 4
    for (int s = 0; s < 16; ++s) {
        const uint4 A0 = *reinterpret_cast<const uint4*>(ab + s * 2048);
        const uint4 A1 = *reinterpret_cast<const uint4*>(ab + s * 2048 + 512);
        const uint2 B0 = *reinterpret_cast<const uint2*>(bb + s * 2048);
        const uint2 B1 = *reinterpret_cast<const uint2*>(bb + s * 2048 + 256);
        mma16816(D[0][0], A0, B0.x, B0.y);
        mma16816(D[0][1], A0, B1.x, B1.y);
        mma16816(D[1][0], A1, B0.x, B0.y);
        mma16816(D[1][1], A1, B1.x, B1.y);
    }
}

__global__ __launch_bounds__(256, 1)
void lstm_kernel(const float* __restrict__ x,     // [8192][32][2]
                 const float* __restrict__ fc_b,  // [128]
                 float* __restrict__ out) {       // [8192][32][128]
    extern __shared__ uint8_t sm[];
    const uint32_t smb = smem_u32(sm);
    const int tx = threadIdx.x;
    const int w = tx >> 5, lane = tx & 31;
    const int wr = w >> 2, wc = w & 3;          // 2 x 4 warp grid
    const int g = lane >> 2, t = lane & 3;
    const uint8_t* gBu = reinterpret_cast<const uint8_t*>(g_Bu);

    float* sbias = reinterpret_cast<float*>(sm + SMBI);
    float* sw0   = reinterpret_cast<float*>(sm + SMW0);
    float* sw1   = reinterpret_cast<float*>(sm + SMW1);
    float* sfcb  = reinterpret_cast<float*>(sm + SMFCB);

    for (int i = tx; i < 1024; i += 256) {
        sbias[i] = g_biasN[i];
        sw0[i]   = g_w0N[i];
        sw1[i]   = g_w1N[i];
    }
    if (tx < 128) sfcb[tx] = fc_b[tx];
    // zero A buf 0 (h_{-1} = 0)
    {
        uint32_t* a32 = reinterpret_cast<uint32_t*>(sm);
        for (int i = tx; i < 8192; i += 256) a32[i] = 0u;
    }
    // prestage chunks 0,1 into ring slots 0,1
    stage_chunk(smb + SMB + 0 * CHUNK_B, gBu + 0 * CHUNK_B, tx);
    stage_chunk(smb + SMB + 1 * CHUNK_B, gBu + 1 * CHUNK_B, tx);

    const int R = blockIdx.x * 64 + wr * 32 + g;   // base row (mf=0, lower half)

    float c_st[4][16];
#pragma unroll
    for (int i = 0; i < 4; ++i)
#pragma unroll
        for (int j = 0; j < 16; ++j) c_st[i][j] = 0.0f;

#pragma unroll 1
    for (int l = 0; l < LSTEPS; ++l) {
        const int p = l & 1;
        const int gcb = l * NC_STEP;
        float2 xv[2][2];
#pragma unroll
        for (int mf = 0; mf < 2; ++mf)
#pragma unroll
            for (int hf = 0; hf < 2; ++hf)
                xv[mf][hf] = __ldg(reinterpret_cast<const float2*>(
                    x + (size_t)(R + mf * 16 + hf * 8) * 64 + l * 2));

        // -------- gates: 4 j-blocks (64 j) x 4 gate chunks, processed in pairs --------
#pragma unroll 1
        for (int jb = 0; jb < 4; ++jb) {
            float Dq[4][2][2][4];
#pragma unroll
            for (int q = 0; q < 4; ++q)
#pragma unroll
                for (int mf = 0; mf < 2; ++mf)
#pragma unroll
                    for (int ntl = 0; ntl < 2; ++ntl)
#pragma unroll
                        for (int i = 0; i < 4; ++i) Dq[q][mf][ntl][i] = 0.0f;

#pragma unroll
            for (int qp = 0; qp < 2; ++qp) {
                __syncthreads();                       // prev pair consumed; A stores visible
                const int gc = gcb + jb * 4 + qp * 2;
                stage_chunk(smb + SMB + ((gc + 2) & 3) * CHUNK_B,
                            gBu + (size_t)((gc + 2) % NC_STEP) * CHUNK_B, tx);
                stage_chunk(smb + SMB + ((gc + 3) & 3) * CHUNK_B,
                            gBu + (size_t)((gc + 3) % NC_STEP) * CHUNK_B, tx);
                CP_WAIT2();                            // current pair resident
                chunk_mma(sm, SMA + p * SMA_BUF, SMB + (gc & 3) * CHUNK_B,
                          wr, wc, lane, Dq[qp * 2]);
                chunk_mma(sm, SMA + p * SMA_BUF, SMB + ((gc + 1) & 3) * CHUNK_B,
                          wr, wc, lane, Dq[qp * 2 + 1]);
            }

            // epilogue: 16 (row,col) positions per thread
            float h[2][2][4];
#pragma unroll
            for (int mf = 0; mf < 2; ++mf) {
#pragma unroll
                for (int ntl = 0; ntl < 2; ++ntl) {
#pragma unroll
                    for (int ci = 0; ci < 4; ++ci) {
                        const int gb = jb * 64 + wc * 16 + ntl * 8 + 2 * t + (ci & 1);
                        const float2 xvv = xv[mf][(ci >> 1) & 1];
                        const float gi = Dq[0][mf][ntl][ci] + sbias[gb]       + xvv.x * sw0[gb]       + xvv.y * sw1[gb];
                        const float gf = Dq[1][mf][ntl][ci] + sbias[256 + gb] + xvv.x * sw0[256 + gb] + xvv.y * sw1[256 + gb];
                        const float gg = Dq[2][mf][ntl][ci] + sbias[512 + gb] + xvv.x * sw0[512 + gb] + xvv.y * sw1[512 + gb];
                        const float go = Dq[3][mf][ntl][ci] + sbias[768 + gb] + xvv.x * sw0[768 + gb] + xvv.y * sw1[768 + gb];
                        const int cs = mf * 8 + ntl * 4 + ci;
                        const float cn = sigf(gf) * c_st[jb][cs] + sigf(gi) * tanhfast(gg);
                        c_st[jb][cs] = cn;
                        h[mf][ntl][ci] = sigf(go) * tanhfast(cn);
                    }
                }
            }
            // store h as next-step A fragments: ktile = jb*4 + wc, m-frags wr*2+mf
            {
                const int kt = jb * 4 + wc;
                uint8_t* base = sm + SMA + (p ^ 1) * SMA_BUF + (size_t)kt * 2048
                              + wr * 1024 + lane * 16;
#pragma unroll
                for (int mf = 0; mf < 2; ++mf) {
                    uint4 v;
                    v.x = ph2(h[mf][0][0], h[mf][0][1]);
                    v.y = ph2(h[mf][0][2], h[mf][0][3]);
                    v.z = ph2(h[mf][1][0], h[mf][1][1]);
                    v.w = ph2(h[mf][1][2], h[mf][1][3]);
                    *reinterpret_cast<uint4*>(base + mf * 512) = v;
                }
            }
        }

        // -------- FC pair: 2 chunks (N=64) on h_t (A buf p^1) --------
        {
            __syncthreads();                           // h_t fragments visible
            const int gc = gcb + 16;
            stage_chunk(smb + SMB + ((gc + 2) & 3) * CHUNK_B,
                        gBu + (size_t)((gc + 2) % NC_STEP) * CHUNK_B, tx);
            stage_chunk(smb + SMB + ((gc + 3) & 3) * CHUNK_B,
                        gBu + (size_t)((gc + 3) % NC_STEP) * CHUNK_B, tx);
            CP_WAIT2();
#pragma unroll
            for (int fcc = 0; fcc < 2; ++fcc) {
                float Df[2][2][4];
#pragma unroll
                for (int mf = 0; mf < 2; ++mf)
#pragma unroll
                    for (int ntl = 0; ntl < 2; ++ntl)
#pragma unroll
                        for (int i = 0; i < 4; ++i) Df[mf][ntl][i] = 0.0f;
                chunk_mma(sm, SMA + (p ^ 1) * SMA_BUF, SMB + ((gc + fcc) & 3) * CHUNK_B,
                          wr, wc, lane, Df);
#pragma unroll
                for (int mf = 0; mf < 2; ++mf) {
#pragma unroll
                    for (int ntl = 0; ntl < 2; ++ntl) {
                        const int cb = fcc * 64 + wc * 16 + ntl * 8 + 2 * t;
                        const int rowm = R + mf * 16;
                        *reinterpret_cast<float2*>(out + (size_t)rowm * (LSTEPS * 128) + l * 128 + cb) =
                            make_float2(Df[mf][ntl][0] + sfcb[cb], Df[mf][ntl][1] + sfcb[cb + 1]);
                        *reinterpret_cast<float2*>(out + (size_t)(rowm + 8) * (LSTEPS * 128) + l * 128 + cb) =
                            make_float2(Df[mf][ntl][2] + sfcb[cb], Df[mf][ntl][3] + sfcb[cb + 1]);
                    }
                }
            }
        }
    }
}

extern "C" void kernel_launch(void* const* d_in, const int* in_sizes, int n_in,
                              void* d_out, int out_size) {
    const float* x    = (const float*)d_in[0];
    const float* W_ih = (const float*)d_in[1];
    const float* W_hh = (const float*)d_in[2];
    const float* b_ih = (const float*)d_in[3];
    const float* b_hh = (const float*)d_in[4];
    const float* fc_w = (const float*)d_in[5];
    const float* fc_b = (const float*)d_in[6];
    float* out = (float*)d_out;

    prep_kernel<<<288, 256>>>(W_ih, W_hh, b_ih, b_hh, fc_w);

    cudaFuncSetAttribute(lstm_kernel, cudaFuncAttributeMaxDynamicSharedMemorySize, SMEM_TOTAL);
    lstm_kernel<<<NCTA, 256, SMEM_TOTAL>>>(x, fc_b, out);
}

// round 14
// speedup vs baseline: 7.3820x; 1.2870x over previous
#include <cuda_runtime.h>
#include <cuda_fp16.h>
#include <cstdint>

// GazeLSTM via mma.sync.m16n8k16 fp16. N=128 super-chunks with gate-pair interleaved
// n-tiles; warp grid 2m x 4n (wm=2, wn=4). tanh.approx activations. 128 CTAs x 256 thr.

#define LSTEPS   32
#define NCTA     128
#define NSUPER   9                     // 8 gate supers (4 jb x 2 qp) + 1 FC super
#define TOTAL_SC (LSTEPS * NSUPER)     // 288
#define SUPER_B  65536                 // 16s x 16nt x 32lane x 8B

// smem byte offsets
#define SMA      0                     // A frags: 2 bufs x 32768
#define SMA_BUF  32768
#define SMB      65536                 // B ring: 2 bufs x 65536 -> ends 196608
#define SMBI     196608
#define SMW0     200704
#define SMW1     204800
#define SMFCB    208896
#define SMEM_TOTAL 209408

// ---------------- prologue-built weights ----------------
__device__ __align__(256) uint32_t g_Bu[NSUPER * (SUPER_B / 4)];
__device__ float g_biasN[1024], g_w0N[1024], g_w1N[1024];

__device__ __forceinline__ uint32_t ph2(float a, float b) {
    __half2 h = __floats2half2_rn(a, b);     // .x = a = low 16 bits (even k)
    return *reinterpret_cast<uint32_t*>(&h);
}

__global__ void prep_kernel(const float* __restrict__ W_ih,
                            const float* __restrict__ W_hh,
                            const float* __restrict__ b_ih,
                            const float* __restrict__ b_hh,
                            const float* __restrict__ fc_w) {
    int idx = blockIdx.x * blockDim.x + threadIdx.x;
    int stride = gridDim.x * blockDim.x;
    // B frag u32 idx in super: ((s*16 + nt)*32 + lane)*2 + reg
    // value: W[k = s*16 + 2*(lane&3) + reg*8 + {0,1}][n-tile nt, n-row = lane>>2]
    // gate supers (c = jb*2 + qp): nt = (jsub<<1)|gm -> gate q = qp*2+gm, j = jb*64+jsub*8+nrow
    for (int u = idx; u < NSUPER * (SUPER_B / 4); u += stride) {
        int c = u >> 14, rem = u & 16383;
        int reg = rem & 1, lane = (rem >> 1) & 31;
        int nt = (rem >> 6) & 15, s = rem >> 10;
        int nrow = lane >> 2;
        int k0 = s * 16 + (lane & 3) * 2 + reg * 8;
        const float* srcrow;
        if (c < 8) {
            int jb = c >> 1, qp = c & 1;
            int q = qp * 2 + (nt & 1);
            int j = jb * 64 + (nt >> 1) * 8 + nrow;
            srcrow = W_hh + (size_t)(q * 256 + j) * 256;
        } else {
            int o = nt * 8 + nrow;
            srcrow = fc_w + (size_t)o * 256;
        }
        g_Bu[u] = ph2(srcrow[k0], srcrow[k0 + 1]);
    }
    for (int g = idx; g < 1024; g += stride) {
        g_biasN[g] = b_ih[g] + b_hh[g];
        g_w0N[g]   = W_ih[g * 2 + 0];
        g_w1N[g]   = W_ih[g * 2 + 1];
    }
}

// ---------------- device helpers ----------------
__device__ __forceinline__ uint32_t smem_u32(const void* p) {
    uint32_t a;
    asm("{ .reg .u64 t; cvta.to.shared.u64 t, %1; cvt.u32.u64 %0, t; }" : "=r"(a) : "l"(p));
    return a;
}
__device__ __forceinline__ void mma16816(float (&d)[4], const uint4& a, uint32_t b0, uint32_t b1) {
    asm("mma.sync.aligned.m16n8k16.row.col.f32.f16.f16.f32 "
        "{%0,%1,%2,%3},{%4,%5,%6,%7},{%8,%9},{%0,%1,%2,%3};"
        : "+f"(d[0]), "+f"(d[1]), "+f"(d[2]), "+f"(d[3])
        : "r"(a.x), "r"(a.y), "r"(a.z), "r"(a.w), "r"(b0), "r"(b1));
}
#define CP16(dst, src) \
    asm volatile("cp.async.cg.shared.global [%0], [%1], 16;" :: "r"(dst), "l"(src) : "memory")
#define CP_COMMIT() asm volatile("cp.async.commit_group;" ::: "memory")
#define CP_WAIT0()  asm volatile("cp.async.wait_group 0;" ::: "memory")

__device__ __forceinline__ void stage_super(uint32_t dst, const uint8_t* gsrc, int tx) {
    uint32_t d = dst + tx * 16;
    uint64_t s = (uint64_t)__cvta_generic_to_global(gsrc) + tx * 16;
#pragma unroll
    for (int i = 0; i < 16; ++i) CP16(d + i * 4096, s + i * 4096);
    CP_COMMIT();
}

__device__ __forceinline__ float tanha(float x) {
    float r;
    asm("tanh.approx.f32 %0, %1;" : "=f"(r) : "f"(x));
    return r;
}
__device__ __forceinline__ float sigt(float x) {      // sigmoid via tanh identity
    return fmaf(tanha(0.5f * x), 0.5f, 0.5f);
}

// one N=128 super: warp = 2 m-frags (wr) x 4 n-tiles (wc), K=256
__device__ __forceinline__ void super_mma(const uint8_t* sm, uint32_t aoff, uint32_t boff,
                                          int wr, int wc, int lane, float (&D)[2][4][4]) {
    const uint8_t* ab = sm + aoff + wr * 1024 + lane * 16;
    const uint8_t* bb = sm + boff + wc * 1024 + lane * 8;
#pragma unroll
    for (int s = 0; s < 16; ++s) {
        const uint4 A0 = *reinterpret_cast<const uint4*>(ab + s * 2048);
        const uint4 A1 = *reinterpret_cast<const uint4*>(ab + s * 2048 + 512);
#pragma unroll
        for (int ntl = 0; ntl < 4; ++ntl) {
            const uint2 B = *reinterpret_cast<const uint2*>(bb + s * 4096 + ntl * 256);
            mma16816(D[0][ntl], A0, B.x, B.y);
            mma16816(D[1][ntl], A1, B.x, B.y);
        }
    }
}

__global__ __launch_bounds__(256, 1)
void lstm_kernel(const float* __restrict__ x,     // [8192][32][2]
                 const float* __restrict__ fc_b,  // [128]
                 float* __restrict__ out) {       // [8192][32][128]
    extern __shared__ uint8_t sm[];
    const uint32_t smb = smem_u32(sm);
    const int tx = threadIdx.x;
    const int w = tx >> 5, lane = tx & 31;
    const int wr = w >> 2, wc = w & 3;          // 2 (m) x 4 (n) warp grid
    const int g = lane >> 2, t = lane & 3;
    const uint8_t* gBu = reinterpret_cast<const uint8_t*>(g_Bu);

    float* sbias = reinterpret_cast<float*>(sm + SMBI);
    float* sw0   = reinterpret_cast<float*>(sm + SMW0);
    float* sw1   = reinterpret_cast<float*>(sm + SMW1);
    float* sfcb  = reinterpret_cast<float*>(sm + SMFCB);

    for (int i = tx; i < 1024; i += 256) {
        sbias[i] = g_biasN[i];
        sw0[i]   = g_w0N[i];
        sw1[i]   = g_w1N[i];
    }
    if (tx < 128) sfcb[tx] = fc_b[tx];
    // zero A buf 0 (h_{-1} = 0)
    {
        uint32_t* a32 = reinterpret_cast<uint32_t*>(sm);
        for (int i = tx; i < 8192; i += 256) a32[i] = 0u;
    }
    // prestage super 0 into slot 0
    stage_super(smb + SMB, gBu, tx);

    const int R = blockIdx.x * 64 + wr * 32 + g;   // base row (mf=0, lower 8-half)

    float c_st[4][16];
#pragma unroll
    for (int i = 0; i < 4; ++i)
#pragma unroll
        for (int j = 0; j < 16; ++j) c_st[i][j] = 0.0f;

#pragma unroll 1
    for (int l = 0; l < LSTEPS; ++l) {
        const int p = l & 1;
        float2 xv[2][2];
#pragma unroll
        for (int mf = 0; mf < 2; ++mf)
#pragma unroll
            for (int hf = 0; hf < 2; ++hf)
                xv[mf][hf] = __ldg(reinterpret_cast<const float2*>(
                    x + (size_t)(R + mf * 16 + hf * 8) * 64 + l * 2));

        // -------- gates: 4 j-blocks x 2 super-chunks (gate pairs) --------
#pragma unroll 1
        for (int jb = 0; jb < 4; ++jb) {
            float Dq[2][2][4][4];
#pragma unroll
            for (int qp = 0; qp < 2; ++qp)
#pragma unroll
                for (int mf = 0; mf < 2; ++mf)
#pragma unroll
                    for (int ntl = 0; ntl < 4; ++ntl)
#pragma unroll
                        for (int i = 0; i < 4; ++i) Dq[qp][mf][ntl][i] = 0.0f;

#pragma unroll
            for (int qp = 0; qp < 2; ++qp) {
                const int sc = l * NSUPER + jb * 2 + qp;
                CP_WAIT0();                 // super sc resident (committed last iter)
                __syncthreads();            // publish sc; prev compute done ring-wide
                if (sc + 1 < TOTAL_SC)
                    stage_super(smb + SMB + ((sc + 1) & 1) * SUPER_B,
                                gBu + (size_t)((sc + 1) % NSUPER) * SUPER_B, tx);
                super_mma(sm, SMA + p * SMA_BUF, SMB + (sc & 1) * SUPER_B,
                          wr, wc, lane, Dq[qp]);
            }

            // epilogue: 16 h per thread (mf x ntj x ci); gates interleaved in ntl
            float h[2][2][4];
#pragma unroll
            for (int mf = 0; mf < 2; ++mf) {
#pragma unroll
                for (int ntj = 0; ntj < 2; ++ntj) {
#pragma unroll
                    for (int ci = 0; ci < 4; ++ci) {
                        const int gb = jb * 64 + wc * 16 + ntj * 8 + 2 * t + (ci & 1);
                        const float2 xvv = xv[mf][(ci >> 1) & 1];
                        const float gi = Dq[0][mf][2*ntj+0][ci] + sbias[gb]       + xvv.x * sw0[gb]       + xvv.y * sw1[gb];
                        const float gf = Dq[0][mf][2*ntj+1][ci] + sbias[256 + gb] + xvv.x * sw0[256 + gb] + xvv.y * sw1[256 + gb];
                        const float gg = Dq[1][mf][2*ntj+0][ci] + sbias[512 + gb] + xvv.x * sw0[512 + gb] + xvv.y * sw1[512 + gb];
                        const float go = Dq[1][mf][2*ntj+1][ci] + sbias[768 + gb] + xvv.x * sw0[768 + gb] + xvv.y * sw1[768 + gb];
                        const int cs = mf * 8 + ntj * 4 + ci;
                        const float cn = sigt(gf) * c_st[jb][cs] + sigt(gi) * tanha(gg);
                        c_st[jb][cs] = cn;
                        h[mf][ntj][ci] = sigt(go) * tanha(cn);
                    }
                }
            }
            // store h as next-step A frags: k-step s = jb*4 + wc, m-frags wr*2+mf
            {
                uint8_t* base = sm + SMA + (p ^ 1) * SMA_BUF
                              + (size_t)(jb * 4 + wc) * 2048 + wr * 1024 + lane * 16;
#pragma unroll
                for (int mf = 0; mf < 2; ++mf) {
                    uint4 v;
                    v.x = ph2(h[mf][0][0], h[mf][0][1]);   // a0: row g,   k 2t,2t+1
                    v.y = ph2(h[mf][0][2], h[mf][0][3]);   // a1: row g+8
                    v.z = ph2(h[mf][1][0], h[mf][1][1]);   // a2: row g,   k +8
                    v.w = ph2(h[mf][1][2], h[mf][1][3]);   // a3: row g+8, k +8
                    *reinterpret_cast<uint4*>(base + mf * 512) = v;
                }
            }
        }

        // -------- FC super (N=128) on h_t (A buf p^1) --------
        {
            const int sc = l * NSUPER + 8;
            CP_WAIT0();
            __syncthreads();               // publish FC B; all epilogue A-stores visible
            if (sc + 1 < TOTAL_SC)
                stage_super(smb + SMB + ((sc + 1) & 1) * SUPER_B,
                            gBu + (size_t)((sc + 1) % NSUPER) * SUPER_B, tx);
            float Df[2][4][4];
#pragma unroll
            for (int mf = 0; mf < 2; ++mf)
#pragma unroll
                for (int ntl = 0; ntl < 4; ++ntl)
#pragma unroll
                    for (int i = 0; i < 4; ++i) Df[mf][ntl][i] = 0.0f;
            super_mma(sm, SMA + (p ^ 1) * SMA_BUF, SMB + (sc & 1) * SUPER_B,
                      wr, wc, lane, Df);
#pragma unroll
            for (int mf = 0; mf < 2; ++mf) {
#pragma unroll
                for (int ntl = 0; ntl < 4; ++ntl) {
                    const int cb = wc * 32 + ntl * 8 + 2 * t;
                    const int rowm = R + mf * 16;
                    *reinterpret_cast<float2*>(out + (size_t)rowm * (LSTEPS * 128) + l * 128 + cb) =
                        make_float2(Df[mf][ntl][0] + sfcb[cb], Df[mf][ntl][1] + sfcb[cb + 1]);
                    *reinterpret_cast<float2*>(out + (size_t)(rowm + 8) * (LSTEPS * 128) + l * 128 + cb) =
                        make_float2(Df[mf][ntl][2] + sfcb[cb], Df[mf][ntl][3] + sfcb[cb + 1]);
                }
            }
        }
    }
}

extern "C" void kernel_launch(void* const* d_in, const int* in_sizes, int n_in,
                              void* d_out, int out_size) {
    const float* x    = (const float*)d_in[0];
    const float* W_ih = (const float*)d_in[1];
    const float* W_hh = (const float*)d_in[2];
    const float* b_ih = (const float*)d_in[3];
    const float* b_hh = (const float*)d_in[4];
    const float* fc_w = (const float*)d_in[5];
    const float* fc_b = (const float*)d_in[6];
    float* out = (float*)d_out;

    prep_kernel<<<288, 256>>>(W_ih, W_hh, b_ih, b_hh, fc_w);

    cudaFuncSetAttribute(lstm_kernel, cudaFuncAttributeMaxDynamicSharedMemorySize, SMEM_TOTAL);
    lstm_kernel<<<NCTA, 256, SMEM_TOTAL>>>(x, fc_b, out);
}

// round 15
// speedup vs baseline: 7.7872x; 1.0549x over previous
#include <cuda_runtime.h>
#include <cuda_fp16.h>
#include <cstdint>

// GazeLSTM via mma.sync.m16n8k16 fp16. N=256 gate supers (gate-interleaved n-tiles),
// K=272 with x/bias folded into the GEMM (k256=x0,k257=x1,k258=1). K-split staging.
// 128 CTAs x 256 thr (2m x 4n warps). Epilogue = pure activations.

#define LSTEPS 32
#define NCTA   128
#define NSTAGE (LSTEPS * 9)            // per step: 4 jb x 2 halves + 1 FC

#define ABUF   34816                   // 17 ktiles x 2048 B
#define SMB    69632                   // after 2 A bufs
#define SLOT   73728                   // B ring slot (holds up to 9 k-steps x 8 KB)
#define SMEM_TOTAL 217088

#define GATE_SUP_B 139264              // 17 s x 8192 B
#define FC_OFF     557056              // 4 * GATE_SUP_B
__device__ __align__(256) uint8_t g_Bu[626688];

__device__ __forceinline__ uint32_t ph2(float a, float b) {
    __half2 h = __floats2half2_rn(a, b);     // .x = a = low 16 bits (even k)
    return *reinterpret_cast<uint32_t*>(&h);
}

__global__ void prep_kernel(const float* __restrict__ W_ih,
                            const float* __restrict__ W_hh,
                            const float* __restrict__ b_ih,
                            const float* __restrict__ b_hh,
                            const float* __restrict__ fc_w,
                            const float* __restrict__ fc_b) {
    int idx = blockIdx.x * blockDim.x + threadIdx.x;
    int stride = gridDim.x * blockDim.x;
    uint32_t* B32 = reinterpret_cast<uint32_t*>(g_Bu);
    // gate supers: u32 idx in super = ((s*16 + ntp)*32 + lane)*4 + sub
    // uint4 = (nt_even r0, nt_even r1, nt_odd r0, nt_odd r1), nt = ntp*2 + (sub>>1)
    for (int e = idx; e < 4 * 34816; e += stride) {
        int c = e / 34816, rem = e % 34816;
        int sub = rem & 3, lane = (rem >> 2) & 31, ntp = (rem >> 7) & 15, s = rem >> 11;
        int nt = ntp * 2 + (sub >> 1), reg = sub & 1;
        int nrow = lane >> 2;
        int k0 = s * 16 + (lane & 3) * 2 + reg * 8;
        int wcq = nt >> 3, ntl = nt & 7, jsl = ntl >> 2, q = ntl & 3;
        int grow = q * 256 + c * 64 + wcq * 16 + jsl * 8 + nrow;
        float v[2];
#pragma unroll
        for (int d = 0; d < 2; ++d) {
            int k = k0 + d;
            if (k < 256)       v[d] = W_hh[(size_t)grow * 256 + k];
            else if (k == 256) v[d] = W_ih[grow * 2 + 0];
            else if (k == 257) v[d] = W_ih[grow * 2 + 1];
            else if (k == 258) v[d] = b_ih[grow] + b_hh[grow];
            else               v[d] = 0.0f;
        }
        B32[e] = ph2(v[0], v[1]);
    }
    // FC super: u32 idx = ((s*8 + ntp)*32 + lane)*4 + sub
    for (int e = idx; e < 17408; e += stride) {
        int sub = e & 3, lane = (e >> 2) & 31, ntp = (e >> 7) & 7, s = e >> 10;
        int nt = ntp * 2 + (sub >> 1), reg = sub & 1;
        int o = nt * 8 + (lane >> 2);
        int k0 = s * 16 + (lane & 3) * 2 + reg * 8;
        float v[2];
#pragma unroll
        for (int d = 0; d < 2; ++d) {
            int k = k0 + d;
            if (k < 256)       v[d] = fc_w[(size_t)o * 256 + k];
            else if (k == 258) v[d] = fc_b[o];
            else               v[d] = 0.0f;
        }
        B32[FC_OFF / 4 + e] = ph2(v[0], v[1]);
    }
}

// ---------------- device helpers ----------------
__device__ __forceinline__ uint32_t smem_u32(const void* p) {
    uint32_t a;
    asm("{ .reg .u64 t; cvta.to.shared.u64 t, %1; cvt.u32.u64 %0, t; }" : "=r"(a) : "l"(p));
    return a;
}
__device__ __forceinline__ void mma16816(float (&d)[4], const uint4& a, uint32_t b0, uint32_t b1) {
    asm("mma.sync.aligned.m16n8k16.row.col.f32.f16.f16.f32 "
        "{%0,%1,%2,%3},{%4,%5,%6,%7},{%8,%9},{%0,%1,%2,%3};"
        : "+f"(d[0]), "+f"(d[1]), "+f"(d[2]), "+f"(d[3])
        : "r"(a.x), "r"(a.y), "r"(a.z), "r"(a.w), "r"(b0), "r"(b1));
}
#define CP16(dst, src) \
    asm volatile("cp.async.cg.shared.global [%0], [%1], 16;" :: "r"(dst), "l"(src) : "memory")
#define CP_COMMIT() asm volatile("cp.async.commit_group;" ::: "memory")
#define CP_WAIT0()  asm volatile("cp.async.wait_group 0;" ::: "memory")

__device__ __forceinline__ void stage_g(uint32_t smb, int gidx, int tx) {
    if (gidx >= NSTAGE) return;
    int st = gidx - (gidx / 9) * 9;
    const uint8_t* src;
    int iters;
    if (st == 8) { src = g_Bu + FC_OFF; iters = 17; }
    else { src = g_Bu + (st >> 1) * GATE_SUP_B + (st & 1) * 73728; iters = (st & 1) ? 16 : 18; }
    uint32_t d = smb + SMB + (uint32_t)(gidx & 1) * SLOT + tx * 16;
    uint64_t s = (uint64_t)__cvta_generic_to_global(src) + tx * 16;
#pragma unroll 6
    for (int i = 0; i < iters; ++i) CP16(d + i * 4096, s + i * 4096);
    CP_COMMIT();
}

__device__ __forceinline__ float tanha(float x) {
    float r;
    asm("tanh.approx.f32 %0, %1;" : "=f"(r) : "f"(x));
    return r;
}
__device__ __forceinline__ float sigt(float x) {
    return fmaf(tanha(0.5f * x), 0.5f, 0.5f);
}

// gate super slice: s = S0..S0+CNT-1 (A global k-tiles), B slot local s
template <int S0, int CNT>
__device__ __forceinline__ void gate_mma(const uint8_t* sm, uint32_t aoff, uint32_t boff,
                                         int wr, int wc, int lane, float (&D)[2][8][4]) {
    const uint8_t* ab = sm + aoff + wr * 1024 + lane * 16 + S0 * 2048;
    const uint8_t* bb = sm + boff + wc * 2048 + lane * 16;
#pragma unroll
    for (int s = 0; s < CNT; ++s) {
        const uint4 A0 = *reinterpret_cast<const uint4*>(ab + s * 2048);
        const uint4 A1 = *reinterpret_cast<const uint4*>(ab + s * 2048 + 512);
#pragma unroll
        for (int np = 0; np < 4; ++np) {
            const uint4 B = *reinterpret_cast<const uint4*>(bb + s * 8192 + np * 512);
            mma16816(D[0][2 * np],     A0, B.x, B.y);
            mma16816(D[0][2 * np + 1], A0, B.z, B.w);
            mma16816(D[1][2 * np],     A1, B.x, B.y);
            mma16816(D[1][2 * np + 1], A1, B.z, B.w);
        }
    }
}

__device__ __forceinline__ void fc_mma(const uint8_t* sm, uint32_t aoff, uint32_t boff,
                                       int wr, int wc, int lane, float (&D)[2][4][4]) {
    const uint8_t* ab = sm + aoff + wr * 1024 + lane * 16;
    const uint8_t* bb = sm + boff + wc * 1024 + lane * 16;
#pragma unroll
    for (int s = 0; s < 17; ++s) {
        const uint4 A0 = *reinterpret_cast<const uint4*>(ab + s * 2048);
        const uint4 A1 = *reinterpret_cast<const uint4*>(ab + s * 2048 + 512);
#pragma unroll
        for (int np = 0; np < 2; ++np) {
            const uint4 B = *reinterpret_cast<const uint4*>(bb + s * 4096 + np * 512);
            mma16816(D[0][2 * np],     A0, B.x, B.y);
            mma16816(D[0][2 * np + 1], A0, B.z, B.w);
            mma16816(D[1][2 * np],     A1, B.x, B.y);
            mma16816(D[1][2 * np + 1], A1, B.z, B.w);
        }
    }
}

__global__ __launch_bounds__(256, 1)
void lstm_kernel(const float* __restrict__ x,     // [8192][32][2]
                 float* __restrict__ out) {       // [8192][32][128]
    extern __shared__ uint8_t sm[];
    const uint32_t smb = smem_u32(sm);
    const int tx = threadIdx.x;
    const int w = tx >> 5, lane = tx & 31;
    const int wr = w >> 2, wc = w & 3;          // 2 (m) x 4 (n)
    const int g = lane >> 2, t = lane & 3;

    // zero both A bufs (h = 0, x/pad slots = 0)
    for (int i = tx; i < 2 * ABUF / 4; i += 256)
        reinterpret_cast<uint32_t*>(sm)[i] = 0u;
    __syncthreads();
    // ones column (k258) in ktile16, both bufs: t==1 lanes of wc==0 warps
    if (wc == 0 && t == 1) {
        const uint32_t one2 = ph2(1.0f, 0.0f);
#pragma unroll
        for (int p2 = 0; p2 < 2; ++p2)
#pragma unroll
            for (int mf = 0; mf < 2; ++mf)
                *reinterpret_cast<uint4*>(sm + p2 * ABUF + 32768 + wr * 1024 + mf * 512 + lane * 16)
                    = make_uint4(one2, one2, 0u, 0u);
    }
    stage_g(smb, 0, tx);

    const int R = blockIdx.x * 64 + wr * 32 + g;

    float c_st[4][16];
#pragma unroll
    for (int i = 0; i < 4; ++i)
#pragma unroll
        for (int j = 0; j < 16; ++j) c_st[i][j] = 0.0f;

#pragma unroll 1
    for (int l = 0; l < LSTEPS; ++l) {
        const int p = l & 1;
        // write x_l into A(p) ktile16 (t==0 lanes of wc==0 warps). Racing readers
        // of this tile multiply these rows by 0, so torn reads are harmless.
        if (wc == 0 && t == 0) {
#pragma unroll
            for (int mf = 0; mf < 2; ++mf) {
                const int r0 = R + mf * 16;
                const float2 xa = __ldg(reinterpret_cast<const float2*>(x + (size_t)r0 * 64 + l * 2));
                const float2 xb = __ldg(reinterpret_cast<const float2*>(x + (size_t)(r0 + 8) * 64 + l * 2));
                *reinterpret_cast<uint4*>(sm + p * ABUF + 32768 + wr * 1024 + mf * 512 + lane * 16)
                    = make_uint4(ph2(xa.x, xa.y), ph2(xb.x, xb.y), 0u, 0u);
            }
        }

#pragma unroll 1
        for (int jb = 0; jb < 4; ++jb) {
            float D[2][8][4];
#pragma unroll
            for (int mf = 0; mf < 2; ++mf)
#pragma unroll
                for (int ntl = 0; ntl < 8; ++ntl)
#pragma unroll
                    for (int i = 0; i < 4; ++i) D[mf][ntl][i] = 0.0f;

            const int g0 = l * 9 + jb * 2;
            // half 0: s 0..8
            CP_WAIT0();
            __syncthreads();
            stage_g(smb, g0 + 1, tx);
            gate_mma<0, 9>(sm, p * ABUF, SMB + (uint32_t)(g0 & 1) * SLOT, wr, wc, lane, D);
            // half 1: s 9..16
            CP_WAIT0();
            __syncthreads();
            stage_g(smb, g0 + 2, tx);
            gate_mma<9, 8>(sm, p * ABUF, SMB + (uint32_t)((g0 + 1) & 1) * SLOT, wr, wc, lane, D);

            // epilogue: gates fully formed in D (x + bias folded in)
            float h[2][2][4];
#pragma unroll
            for (int mf = 0; mf < 2; ++mf) {
#pragma unroll
                for (int jsl = 0; jsl < 2; ++jsl) {
#pragma unroll
                    for (int ci = 0; ci < 4; ++ci) {
                        const float gi = D[mf][jsl * 4 + 0][ci];
                        const float gf = D[mf][jsl * 4 + 1][ci];
                        const float gg = D[mf][jsl * 4 + 2][ci];
                        const float go = D[mf][jsl * 4 + 3][ci];
                        const int cs = mf * 8 + jsl * 4 + ci;
                        const float cn = sigt(gf) * c_st[jb][cs] + sigt(gi) * tanha(gg);
                        c_st[jb][cs] = cn;
                        h[mf][jsl][ci] = sigt(go) * tanha(cn);
                    }
                }
            }
            // store h as next-step A frags: ktile jb*4 + wc, m-frags wr*2+mf
            {
                uint8_t* base = sm + (p ^ 1) * ABUF + (size_t)(jb * 4 + wc) * 2048
                              + wr * 1024 + lane * 16;
#pragma unroll
                for (int mf = 0; mf < 2; ++mf) {
                    uint4 v;
                    v.x = ph2(h[mf][0][0], h[mf][0][1]);
                    v.y = ph2(h[mf][0][2], h[mf][0][3]);
                    v.z = ph2(h[mf][1][0], h[mf][1][1]);
                    v.w = ph2(h[mf][1][2], h[mf][1][3]);
                    *reinterpret_cast<uint4*>(base + mf * 512) = v;
                }
            }
        }

        // -------- FC super (N=128, fc_b folded) on h_t = A(p^1) --------
        {
            const int gf8 = l * 9 + 8;
            CP_WAIT0();
            __syncthreads();
            stage_g(smb, gf8 + 1, tx);
            float Df[2][4][4];
#pragma unroll
            for (int mf = 0; mf < 2; ++mf)
#pragma unroll
                for (int ntl = 0; ntl < 4; ++ntl)
#pragma unroll
                    for (int i = 0; i < 4; ++i) Df[mf][ntl][i] = 0.0f;
            fc_mma(sm, (p ^ 1) * ABUF, SMB + (uint32_t)(gf8 & 1) * SLOT, wr, wc, lane, Df);
#pragma unroll
            for (int mf = 0; mf < 2; ++mf) {
#pragma unroll
                for (int ntl = 0; ntl < 4; ++ntl) {
                    const int cb = wc * 32 + ntl * 8 + 2 * t;
                    const int rowm = R + mf * 16;
                    *reinterpret_cast<float2*>(out + (size_t)rowm * (LSTEPS * 128) + l * 128 + cb)
                        = make_float2(Df[mf][ntl][0], Df[mf][ntl][1]);
                    *reinterpret_cast<float2*>(out + (size_t)(rowm + 8) * (LSTEPS * 128) + l * 128 + cb)
                        = make_float2(Df[mf][ntl][2], Df[mf][ntl][3]);
                }
            }
        }
    }
}

extern "C" void kernel_launch(void* const* d_in, const int* in_sizes, int n_in,
                              void* d_out, int out_size) {
    const float* x    = (const float*)d_in[0];
    const float* W_ih = (const float*)d_in[1];
    const float* W_hh = (const float*)d_in[2];
    const float* b_ih = (const float*)d_in[3];
    const float* b_hh = (const float*)d_in[4];
    const float* fc_w = (const float*)d_in[5];
    const float* fc_b = (const float*)d_in[6];
    float* out = (float*)d_out;

    prep_kernel<<<288, 256>>>(W_ih, W_hh, b_ih, b_hh, fc_w, fc_b);

    cudaFuncSetAttribute(lstm_kernel, cudaFuncAttributeMaxDynamicSharedMemorySize, SMEM_TOTAL);
    lstm_kernel<<<NCTA, 256, SMEM_TOTAL>>>(x, out);
}

// round 16
// speedup vs baseline: 8.3434x; 1.0714x over previous
#include <cuda_runtime.h>
#include <cuda_fp16.h>
#include <cstdint>

// GazeLSTM via mma.sync.m16n8k16 fp16. N=256 gate supers, K=272 (x/bias folded in).
// R16: software-pipelined epilogue — gate epilogue of jb overlaps MMA issue of jb+1.
// 128 CTAs x 256 thr (2m x 4n warps).

#define LSTEPS 32
#define NCTA   128
#define NSTAGE (LSTEPS * 9)            // per step: 4 jb x 2 halves + 1 FC

#define ABUF   34816                   // 17 ktiles x 2048 B
#define SMB    69632                   // after 2 A bufs
#define SLOT   73728                   // B ring slot (up to 9 k-steps x 8 KB)
#define SMEM_TOTAL 217088

#define GATE_SUP_B 139264              // 17 s x 8192 B
#define FC_OFF     557056              // 4 * GATE_SUP_B
__device__ __align__(256) uint8_t g_Bu[626688];

__device__ __forceinline__ uint32_t ph2(float a, float b) {
    __half2 h = __floats2half2_rn(a, b);     // .x = a = low 16 bits (even k)
    return *reinterpret_cast<uint32_t*>(&h);
}

__global__ void prep_kernel(const float* __restrict__ W_ih,
                            const float* __restrict__ W_hh,
                            const float* __restrict__ b_ih,
                            const float* __restrict__ b_hh,
                            const float* __restrict__ fc_w,
                            const float* __restrict__ fc_b) {
    int idx = blockIdx.x * blockDim.x + threadIdx.x;
    int stride = gridDim.x * blockDim.x;
    uint32_t* B32 = reinterpret_cast<uint32_t*>(g_Bu);
    // gate supers: u32 idx in super = ((s*16 + ntp)*32 + lane)*4 + sub
    for (int e = idx; e < 4 * 34816; e += stride) {
        int c = e / 34816, rem = e % 34816;
        int sub = rem & 3, lane = (rem >> 2) & 31, ntp = (rem >> 7) & 15, s = rem >> 11;
        int nt = ntp * 2 + (sub >> 1), reg = sub & 1;
        int nrow = lane >> 2;
        int k0 = s * 16 + (lane & 3) * 2 + reg * 8;
        int wcq = nt >> 3, ntl = nt & 7, jsl = ntl >> 2, q = ntl & 3;
        int grow = q * 256 + c * 64 + wcq * 16 + jsl * 8 + nrow;
        float v[2];
#pragma unroll
        for (int d = 0; d < 2; ++d) {
            int k = k0 + d;
            if (k < 256)       v[d] = W_hh[(size_t)grow * 256 + k];
            else if (k == 256) v[d] = W_ih[grow * 2 + 0];
            else if (k == 257) v[d] = W_ih[grow * 2 + 1];
            else if (k == 258) v[d] = b_ih[grow] + b_hh[grow];
            else               v[d] = 0.0f;
        }
        B32[e] = ph2(v[0], v[1]);
    }
    // FC super: u32 idx = ((s*8 + ntp)*32 + lane)*4 + sub
    for (int e = idx; e < 17408; e += stride) {
        int sub = e & 3, lane = (e >> 2) & 31, ntp = (e >> 7) & 7, s = e >> 10;
        int nt = ntp * 2 + (sub >> 1), reg = sub & 1;
        int o = nt * 8 + (lane >> 2);
        int k0 = s * 16 + (lane & 3) * 2 + reg * 8;
        float v[2];
#pragma unroll
        for (int d = 0; d < 2; ++d) {
            int k = k0 + d;
            if (k < 256)       v[d] = fc_w[(size_t)o * 256 + k];
            else if (k == 258) v[d] = fc_b[o];
            else               v[d] = 0.0f;
        }
        B32[FC_OFF / 4 + e] = ph2(v[0], v[1]);
    }
}

// ---------------- device helpers ----------------
__device__ __forceinline__ uint32_t smem_u32(const void* p) {
    uint32_t a;
    asm("{ .reg .u64 t; cvta.to.shared.u64 t, %1; cvt.u32.u64 %0, t; }" : "=r"(a) : "l"(p));
    return a;
}
__device__ __forceinline__ void mma16816(float (&d)[4], const uint4& a, uint32_t b0, uint32_t b1) {
    asm("mma.sync.aligned.m16n8k16.row.col.f32.f16.f16.f32 "
        "{%0,%1,%2,%3},{%4,%5,%6,%7},{%8,%9},{%0,%1,%2,%3};"
        : "+f"(d[0]), "+f"(d[1]), "+f"(d[2]), "+f"(d[3])
        : "r"(a.x), "r"(a.y), "r"(a.z), "r"(a.w), "r"(b0), "r"(b1));
}
#define CP16(dst, src) \
    asm volatile("cp.async.cg.shared.global [%0], [%1], 16;" :: "r"(dst), "l"(src) : "memory")
#define CP_COMMIT() asm volatile("cp.async.commit_group;" ::: "memory")
#define CP_WAIT0()  asm volatile("cp.async.wait_group 0;" ::: "memory")

__device__ __forceinline__ void stage_g(uint32_t smb, int gidx, int tx) {
    if (gidx >= NSTAGE) return;
    int st = gidx - (gidx / 9) * 9;
    const uint8_t* src;
    int iters;
    if (st == 8) { src = g_Bu + FC_OFF; iters = 17; }
    else { src = g_Bu + (st >> 1) * GATE_SUP_B + (st & 1) * 73728; iters = (st & 1) ? 16 : 18; }
    uint32_t d = smb + SMB + (uint32_t)(gidx & 1) * SLOT + tx * 16;
    uint64_t s = (uint64_t)__cvta_generic_to_global(src) + tx * 16;
#pragma unroll 6
    for (int i = 0; i < iters; ++i) CP16(d + i * 4096, s + i * 4096);
    CP_COMMIT();
}

__device__ __forceinline__ float tanha(float x) {
    float r;
    asm("tanh.approx.f32 %0, %1;" : "=f"(r) : "f"(x));
    return r;
}
__device__ __forceinline__ float sigt(float x) {
    return fmaf(tanha(0.5f * x), 0.5f, 0.5f);
}

template <int S0, int CNT>
__device__ __forceinline__ void gate_mma(const uint8_t* sm, uint32_t aoff, uint32_t boff,
                                         int wr, int wc, int lane, float (&D)[2][8][4]) {
    const uint8_t* ab = sm + aoff + wr * 1024 + lane * 16 + S0 * 2048;
    const uint8_t* bb = sm + boff + wc * 2048 + lane * 16;
#pragma unroll
    for (int s = 0; s < CNT; ++s) {
        const uint4 A0 = *reinterpret_cast<const uint4*>(ab + s * 2048);
        const uint4 A1 = *reinterpret_cast<const uint4*>(ab + s * 2048 + 512);
#pragma unroll
        for (int np = 0; np < 4; ++np) {
            const uint4 B = *reinterpret_cast<const uint4*>(bb + s * 8192 + np * 512);
            mma16816(D[0][2 * np],     A0, B.x, B.y);
            mma16816(D[0][2 * np + 1], A0, B.z, B.w);
            mma16816(D[1][2 * np],     A1, B.x, B.y);
            mma16816(D[1][2 * np + 1], A1, B.z, B.w);
        }
    }
}

__device__ __forceinline__ void fc_mma(const uint8_t* sm, uint32_t aoff, uint32_t boff,
                                       int wr, int wc, int lane, float (&D)[2][4][4]) {
    const uint8_t* ab = sm + aoff + wr * 1024 + lane * 16;
    const uint8_t* bb = sm + boff + wc * 1024 + lane * 16;
#pragma unroll
    for (int s = 0; s < 17; ++s) {
        const uint4 A0 = *reinterpret_cast<const uint4*>(ab + s * 2048);
        const uint4 A1 = *reinterpret_cast<const uint4*>(ab + s * 2048 + 512);
#pragma unroll
        for (int np = 0; np < 2; ++np) {
            const uint4 B = *reinterpret_cast<const uint4*>(bb + s * 4096 + np * 512);
            mma16816(D[0][2 * np],     A0, B.x, B.y);
            mma16816(D[0][2 * np + 1], A0, B.z, B.w);
            mma16816(D[1][2 * np],     A1, B.x, B.y);
            mma16816(D[1][2 * np + 1], A1, B.z, B.w);
        }
    }
}

// gate epilogue for j-block jb (runtime): D -> c,h; h stored as A(pn) fragments
__device__ __forceinline__ void gate_epi(uint8_t* sm, int jb, float (&D)[2][8][4],
                                         float* c_jb, int pn, int wr, int wc, int lane) {
    float h[2][2][4];
#pragma unroll
    for (int mf = 0; mf < 2; ++mf) {
#pragma unroll
        for (int jsl = 0; jsl < 2; ++jsl) {
#pragma unroll
            for (int ci = 0; ci < 4; ++ci) {
                const float gi = D[mf][jsl * 4 + 0][ci];
                const float gf = D[mf][jsl * 4 + 1][ci];
                const float gg = D[mf][jsl * 4 + 2][ci];
                const float go = D[mf][jsl * 4 + 3][ci];
                const int cs = mf * 8 + jsl * 4 + ci;
                const float cn = sigt(gf) * c_jb[cs] + sigt(gi) * tanha(gg);
                c_jb[cs] = cn;
                h[mf][jsl][ci] = sigt(go) * tanha(cn);
            }
        }
    }
    uint8_t* base = sm + pn * ABUF + (size_t)(jb * 4 + wc) * 2048 + wr * 1024 + lane * 16;
#pragma unroll
    for (int mf = 0; mf < 2; ++mf) {
        uint4 v;
        v.x = ph2(h[mf][0][0], h[mf][0][1]);
        v.y = ph2(h[mf][0][2], h[mf][0][3]);
        v.z = ph2(h[mf][1][0], h[mf][1][1]);
        v.w = ph2(h[mf][1][2], h[mf][1][3]);
        *reinterpret_cast<uint4*>(base + mf * 512) = v;
    }
}

#define ZERO_D(D) \
    { _Pragma("unroll") for (int _m = 0; _m < 2; ++_m) \
      _Pragma("unroll") for (int _n = 0; _n < 8; ++_n) \
      _Pragma("unroll") for (int _i = 0; _i < 4; ++_i) (D)[_m][_n][_i] = 0.0f; }

__global__ __launch_bounds__(256, 1)
void lstm_kernel(const float* __restrict__ x,     // [8192][32][2]
                 float* __restrict__ out) {       // [8192][32][128]
    extern __shared__ uint8_t sm[];
    const uint32_t smb = smem_u32(sm);
    const int tx = threadIdx.x;
    const int w = tx >> 5, lane = tx & 31;
    const int wr = w >> 2, wc = w & 3;          // 2 (m) x 4 (n)
    const int g = lane >> 2, t = lane & 3;

    // zero both A bufs
    for (int i = tx; i < 2 * ABUF / 4; i += 256)
        reinterpret_cast<uint32_t*>(sm)[i] = 0u;
    __syncthreads();
    // ones column (k258) in ktile16, both bufs
    if (wc == 0 && t == 1) {
        const uint32_t one2 = ph2(1.0f, 0.0f);
#pragma unroll
        for (int p2 = 0; p2 < 2; ++p2)
#pragma unroll
            for (int mf = 0; mf < 2; ++mf)
                *reinterpret_cast<uint4*>(sm + p2 * ABUF + 32768 + wr * 1024 + mf * 512 + lane * 16)
                    = make_uint4(one2, one2, 0u, 0u);
    }
    stage_g(smb, 0, tx);

    const int R = blockIdx.x * 64 + wr * 32 + g;

    float c_st[4][16];
#pragma unroll
    for (int i = 0; i < 4; ++i)
#pragma unroll
        for (int j = 0; j < 16; ++j) c_st[i][j] = 0.0f;

    float DA[2][8][4], DB[2][8][4];

#pragma unroll 1
    for (int l = 0; l < LSTEPS; ++l) {
        const int p = l & 1;
        const int base = l * 9;
        // write x_l into A(p) ktile16 (read no earlier than half1, after a sync)
        if (wc == 0 && t == 0) {
#pragma unroll
            for (int mf = 0; mf < 2; ++mf) {
                const int r0 = R + mf * 16;
                const float2 xa = __ldg(reinterpret_cast<const float2*>(x + (size_t)r0 * 64 + l * 2));
                const float2 xb = __ldg(reinterpret_cast<const float2*>(x + (size_t)(r0 + 8) * 64 + l * 2));
                *reinterpret_cast<uint4*>(sm + p * ABUF + 32768 + wr * 1024 + mf * 512 + lane * 16)
                    = make_uint4(ph2(xa.x, xa.y), ph2(xb.x, xb.y), 0u, 0u);
            }
        }

        // -------- gates, software-pipelined in jb pairs --------
#pragma unroll 1
        for (int jbp = 0; jbp < 2; ++jbp) {
            const int sc = base + jbp * 4;
            // super A = jb 2*jbp
            ZERO_D(DA);
            CP_WAIT0(); __syncthreads();
            stage_g(smb, sc + 1, tx);
            gate_mma<0, 9>(sm, p * ABUF, SMB + (uint32_t)(sc & 1) * SLOT, wr, wc, lane, DA);
            if (jbp > 0)  // epilogue of jb 1 (odd of previous pair) under DA's MMA drain
                gate_epi(sm, 2 * jbp - 1, DB, c_st[2 * jbp - 1], p ^ 1, wr, wc, lane);
            CP_WAIT0(); __syncthreads();
            stage_g(smb, sc + 2, tx);
            gate_mma<9, 8>(sm, p * ABUF, SMB + (uint32_t)((sc + 1) & 1) * SLOT, wr, wc, lane, DA);

            // super B = jb 2*jbp+1
            ZERO_D(DB);
            CP_WAIT0(); __syncthreads();
            stage_g(smb, sc + 3, tx);
            gate_mma<0, 9>(sm, p * ABUF, SMB + (uint32_t)((sc + 2) & 1) * SLOT, wr, wc, lane, DB);
            gate_epi(sm, 2 * jbp, DA, c_st[2 * jbp], p ^ 1, wr, wc, lane);  // hidden under DB drain
            CP_WAIT0(); __syncthreads();
            stage_g(smb, sc + 4, tx);
            gate_mma<9, 8>(sm, p * ABUF, SMB + (uint32_t)((sc + 3) & 1) * SLOT, wr, wc, lane, DB);
        }
        // last epilogue (jb 3) must precede the barrier that publishes A(p^1) to FC
        gate_epi(sm, 3, DB, c_st[3], p ^ 1, wr, wc, lane);

        // -------- FC super (N=128, fc_b folded) on h_t = A(p^1) --------
        {
            const int gf8 = base + 8;
            CP_WAIT0(); __syncthreads();
            stage_g(smb, gf8 + 1, tx);
            float Df[2][4][4];
#pragma unroll
            for (int mf = 0; mf < 2; ++mf)
#pragma unroll
                for (int ntl = 0; ntl < 4; ++ntl)
#pragma unroll
                    for (int i = 0; i < 4; ++i) Df[mf][ntl][i] = 0.0f;
            fc_mma(sm, (p ^ 1) * ABUF, SMB + (uint32_t)(gf8 & 1) * SLOT, wr, wc, lane, Df);
#pragma unroll
            for (int mf = 0; mf < 2; ++mf) {
#pragma unroll
                for (int ntl = 0; ntl < 4; ++ntl) {
                    const int cb = wc * 32 + ntl * 8 + 2 * t;
                    const int rowm = R + mf * 16;
                    *reinterpret_cast<float2*>(out + (size_t)rowm * (LSTEPS * 128) + l * 128 + cb)
                        = make_float2(Df[mf][ntl][0], Df[mf][ntl][1]);
                    *reinterpret_cast<float2*>(out + (size_t)(rowm + 8) * (LSTEPS * 128) + l * 128 + cb)
                        = make_float2(Df[mf][ntl][2], Df[mf][ntl][3]);
                }
            }
        }
    }
}

extern "C" void kernel_launch(void* const* d_in, const int* in_sizes, int n_in,
                              void* d_out, int out_size) {
    const float* x    = (const float*)d_in[0];
    const float* W_ih = (const float*)d_in[1];
    const float* W_hh = (const float*)d_in[2];
    const float* b_ih = (const float*)d_in[3];
    const float* b_hh = (const float*)d_in[4];
    const float* fc_w = (const float*)d_in[5];
    const float* fc_b = (const float*)d_in[6];
    float* out = (float*)d_out;

    prep_kernel<<<288, 256>>>(W_ih, W_hh, b_ih, b_hh, fc_w, fc_b);

    cudaFuncSetAttribute(lstm_kernel, cudaFuncAttributeMaxDynamicSharedMemorySize, SMEM_TOTAL);
    lstm_kernel<<<NCTA, 256, SMEM_TOTAL>>>(x, out);
}